// round 8
// baseline (speedup 1.0000x reference)
#include <cuda_runtime.h>
#include <cstdint>
#include <math.h>

#define SQ 2048
#define NH 16
#define DM 1024
#define DH 64

__device__ float g_q[NH * SQ * DH];       // pre-scaled by 1/8, tf32-rounded
__device__ float g_k[NH * SQ * DH];
__device__ float g_v[NH * SQ * DH];
__device__ float g_vt[NH * DH * SQ];      // V^T: [h][e][s], tf32-rounded
__device__ float g_z[NH * SQ * DH];
__device__ float g_wt[3][NH * DH * DM];   // W^T, tf32-rounded
__device__ float g_wot[NH * DM * DH];     // W_O^T, tf32-rounded

__device__ __forceinline__ uint32_t smem_u32(const void* p) {
    uint32_t a;
    asm("{ .reg .u64 t; cvta.to.shared.u64 t, %1; cvt.u32.u64 %0, t; }" : "=r"(a) : "l"(p));
    return a;
}
#define SWZ128(x) ((x) ^ (((x) >> 3) & 0x70))

__device__ __forceinline__ float to_tf32(float x) {
    float y;
    asm("cvt.rna.tf32.f32 %0, %1;" : "=f"(y) : "f"(x));
    return y;
}
__device__ __forceinline__ void ldsm_x4(uint32_t& r0, uint32_t& r1, uint32_t& r2,
                                        uint32_t& r3, uint32_t addr) {
    asm volatile("ldmatrix.sync.aligned.m8n8.x4.shared.b16 {%0,%1,%2,%3}, [%4];"
                 : "=r"(r0), "=r"(r1), "=r"(r2), "=r"(r3) : "r"(addr));
}
__device__ __forceinline__ void mma_tf32(float* c, const uint32_t* a,
                                         uint32_t b0, uint32_t b1) {
    asm volatile(
        "mma.sync.aligned.m16n8k8.row.col.f32.tf32.tf32.f32 "
        "{%0,%1,%2,%3}, {%4,%5,%6,%7}, {%8,%9}, {%0,%1,%2,%3};"
        : "+f"(c[0]), "+f"(c[1]), "+f"(c[2]), "+f"(c[3])
        : "r"(a[0]), "r"(a[1]), "r"(a[2]), "r"(a[3]), "r"(b0), "r"(b1));
}
#define CP_ASYNC16(dst, src) \
    asm volatile("cp.async.cg.shared.global [%0], [%1], 16;" :: "r"(dst), "l"(src))
#define CP_COMMIT() asm volatile("cp.async.commit_group;" ::: "memory")
#define CP_WAIT(n)  asm volatile("cp.async.wait_group %0;" :: "n"(n) : "memory")

// ---------------- W transpose (+tf32 round) -----------------------------------
__global__ void transpose_w_kernel(const float* __restrict__ WQ, const float* __restrict__ WK,
                                   const float* __restrict__ WV, const float* __restrict__ WO)
{
    __shared__ float t[32][33];
    const int m = blockIdx.y >> 4, h = blockIdx.y & 15;
    const float* src; float* dst; int R, C;
    if (m == 0)      { src = WQ + (size_t)h*DM*DH; dst = g_wt[0] + (size_t)h*DH*DM; R = DM; C = DH; }
    else if (m == 1) { src = WK + (size_t)h*DM*DH; dst = g_wt[1] + (size_t)h*DH*DM; R = DM; C = DH; }
    else if (m == 2) { src = WV + (size_t)h*DM*DH; dst = g_wt[2] + (size_t)h*DH*DM; R = DM; C = DH; }
    else             { src = WO + (size_t)h*DH*DM; dst = g_wot   + (size_t)h*DM*DH; R = DH; C = DM; }
    const int nrt = R / 32, rt = blockIdx.x % nrt, ct = blockIdx.x / nrt;
    const int x = ct * 32 + threadIdx.x;
    #pragma unroll
    for (int j = 0; j < 4; j++)
        t[threadIdx.y + j*8][threadIdx.x] =
            to_tf32(src[(size_t)(rt*32 + threadIdx.y + j*8) * C + x]);
    __syncthreads();
    const int xo = rt * 32 + threadIdx.x;
    #pragma unroll
    for (int j = 0; j < 4; j++)
        dst[(size_t)(ct*32 + threadIdx.y + j*8) * R + xo] = t[threadIdx.x][threadIdx.y + j*8];
}

// ---------------- V transpose: g_v [h][s][e] -> g_vt [h][e][s] -----------------
__global__ void vtrans_kernel()
{
    __shared__ float t[32][33];
    const int h = blockIdx.z;
    const int s0 = blockIdx.x * 32, e0 = blockIdx.y * 32;
    #pragma unroll
    for (int j = 0; j < 4; j++)
        t[threadIdx.y + j*8][threadIdx.x] =
            g_v[((size_t)h*SQ + s0 + threadIdx.y + j*8) * DH + e0 + threadIdx.x];
    __syncthreads();
    #pragma unroll
    for (int j = 0; j < 4; j++)
        g_vt[((size_t)h*DH + e0 + threadIdx.y + j*8) * SQ + s0 + threadIdx.x] =
            t[threadIdx.x][threadIdx.y + j*8];
}

// ---------------- Projection via HMMA tf32, 3-stage cp.async -------------------
__global__ __launch_bounds__(256, 1) void proj_mma_kernel(
    const float* __restrict__ xq, const float* __restrict__ xk, const float* __restrict__ xv,
    const float* __restrict__ bQ, const float* __restrict__ bK, const float* __restrict__ bV)
{
    extern __shared__ uint8_t dsm[];
    const uint32_t sA = smem_u32(dsm);
    const uint32_t sB = sA + 49152;

    const int tid = threadIdx.x, w = tid >> 5, lane = tid & 31;
    const int h = blockIdx.y, which = blockIdx.z;
    const int s0 = blockIdx.x * 128;

    const float* X    = (which == 0) ? xq : (which == 1) ? xk : xv;
    const float* bias = (which == 0) ? bQ : (which == 1) ? bK : bV;
    const float* WT   = g_wt[which] + (size_t)h * DH * DM;
    float* out        = (which == 0) ? g_q : (which == 1) ? g_k : g_v;

    const int mw = w * 16;
    const int g  = lane >> 3, l7 = lane & 7;

    auto prefetch = [&](int c) {
        const int k0 = c * 32;
        const uint32_t ab = sA + (uint32_t)((c % 3) * 16384);
        const uint32_t bb = sB + (uint32_t)((c % 3) * 8192);
        #pragma unroll
        for (int i = 0; i < 4; i++) {
            int idx = tid + i * 256, r = idx >> 3, q = idx & 7;
            CP_ASYNC16(ab + SWZ128((uint32_t)(r*128 + q*16)),
                       &X[(((size_t)(s0 + r)) * NH + h) * DM + k0 + q*4]);
        }
        #pragma unroll
        for (int i = 0; i < 2; i++) {
            int idx = tid + i * 256, n = idx >> 3, q = idx & 7;
            CP_ASYNC16(bb + SWZ128((uint32_t)(n*128 + q*16)),
                       &WT[(size_t)n * DM + k0 + q*4]);
        }
    };

    float acc[8][4] = {};

    prefetch(0); CP_COMMIT();
    prefetch(1); CP_COMMIT();

    #pragma unroll 1
    for (int c = 0; c < 32; c++) {
        CP_WAIT(1);
        __syncthreads();
        if (c + 2 < 32) prefetch(c + 2);
        CP_COMMIT();

        const uint32_t sbA = sA + (uint32_t)((c % 3) * 16384);
        const uint32_t sbB = sB + (uint32_t)((c % 3) * 8192);
        #pragma unroll
        for (int kk = 0; kk < 4; kk++) {
            const int kb = kk * 32;
            uint32_t a[4];
            {
                int row = mw + ((g & 1) << 3) + l7;
                int byo = kb + ((g >> 1) << 4);
                ldsm_x4(a[0], a[1], a[2], a[3], sbA + SWZ128((uint32_t)(row*128 + byo)));
            }
            uint32_t b[16];
            #pragma unroll
            for (int nb = 0; nb < 4; nb++) {
                int row = nb * 16 + ((g >> 1) << 3) + l7;
                int byo = kb + ((g & 1) << 4);
                ldsm_x4(b[nb*4+0], b[nb*4+1], b[nb*4+2], b[nb*4+3],
                        sbB + SWZ128((uint32_t)(row*128 + byo)));
            }
            #pragma unroll
            for (int ni = 0; ni < 8; ni++)
                mma_tf32(acc[ni], a, b[(ni >> 1)*4 + (ni & 1)*2],
                                     b[(ni >> 1)*4 + (ni & 1)*2 + 1]);
        }
    }

    const int r0 = mw + (lane >> 2);
    const int ec = (lane & 3) * 2;

    #pragma unroll
    for (int ni = 0; ni < 8; ni++) {
        float bv0 = bias[h * DH + ni*8 + ec];
        float bv1 = bias[h * DH + ni*8 + ec + 1];
        acc[ni][0] += bv0; acc[ni][1] += bv1;
        acc[ni][2] += bv0; acc[ni][3] += bv1;
    }

    if (which < 2) {
        const float L2B = 0.41524101186092029f;
        #pragma unroll
        for (int ni = 0; ni < 4; ni++) {
            #pragma unroll
            for (int cc = 0; cc < 2; cc++) {
                int j = ni*8 + ec + cc;
                float invf = exp2f(-(float)j * L2B);
                #pragma unroll
                for (int rr = 0; rr < 2; rr++) {
                    float pos = (float)(s0 + r0 + rr*8);
                    float sn, cs; sincosf(pos * invf, &sn, &cs);
                    int ci = rr*2 + cc;
                    float x = acc[ni][ci], y = acc[ni+4][ci];
                    acc[ni][ci]   = x*cs - y*sn;
                    acc[ni+4][ci] = y*cs + x*sn;
                }
            }
        }
    }

    const float osc = (which == 0) ? 0.125f : 1.0f;   // fold attention scale into Q
    #pragma unroll
    for (int ni = 0; ni < 8; ni++) {
        int e = ni*8 + ec;
        *(float2*)&out[((size_t)h*SQ + s0 + r0    ) * DH + e] =
            make_float2(to_tf32(acc[ni][0]*osc), to_tf32(acc[ni][1]*osc));
        *(float2*)&out[((size_t)h*SQ + s0 + r0 + 8) * DH + e] =
            make_float2(to_tf32(acc[ni][2]*osc), to_tf32(acc[ni][3]*osc));
    }
}

// ---------------- Attention via HMMA tf32, m32/warp, 128-row q-tiles -----------
// grid (8 pairs, 16 heads), 128 threads (4 warps x m32).
// dyn smem: Q @0 (32KB), P @32768 (32KB), K @65536 (2x16KB), V @98304 (2x16KB) = 128KB
__global__ __launch_bounds__(128, 1) void attn_mma_kernel()
{
    extern __shared__ uint8_t dsm[];
    const uint32_t sQ = smem_u32(dsm);
    const uint32_t sP = sQ + 32768;
    const uint32_t sK = sQ + 65536;
    const uint32_t sV = sQ + 98304;

    const int tid = threadIdx.x, w = tid >> 5, lane = tid & 31;
    const int h = blockIdx.y;
    const int g = lane >> 3, l7 = lane & 7;
    const int mw = w * 32;
    const int r_loc = lane >> 2, ec = (lane & 3) * 2;

    auto load_kv = [&](int kt) {
        const int kk0 = kt * 64;
        const uint32_t boff = (uint32_t)((kt & 1) * 16384);
        #pragma unroll
        for (int i = 0; i < 8; i++) {
            int idx = tid + i * 128, r = idx >> 4, q = idx & 15;
            uint32_t off = boff + (uint32_t)((q>>3)*8192) + SWZ128((uint32_t)(r*128 + (q&7)*16));
            CP_ASYNC16(sK + off, &g_k [((size_t)h*SQ + kk0 + r) * DH + q*4]);
            CP_ASYNC16(sV + off, &g_vt[((size_t)h*DH + r) * SQ + kk0 + q*4]);
        }
    };

    for (int rep = 0; rep < 2; rep++) {
        const int qt = rep ? (15 - (int)blockIdx.x) : (int)blockIdx.x;
        const int q0 = qt * 128;
        const int kt_max = 2 * qt + 1;

        __syncthreads();
        #pragma unroll
        for (int i = 0; i < 16; i++) {   // Q tile 128x64
            int idx = tid + i * 128, r = idx >> 4, q = idx & 15;
            uint32_t off = (uint32_t)((q>>3)*16384) + SWZ128((uint32_t)(r*128 + (q&7)*16));
            CP_ASYNC16(sQ + off, &g_q[((size_t)h*SQ + q0 + r) * DH + q*4]);
        }
        CP_COMMIT();
        load_kv(0);
        CP_COMMIT();
        CP_WAIT(1);
        __syncthreads();

        uint32_t qa[8][2][4];
        #pragma unroll
        for (int ds = 0; ds < 8; ds++)
            #pragma unroll
            for (int hh = 0; hh < 2; hh++) {
                int row = mw + hh*16 + ((g & 1) << 3) + l7;
                int byo = (ds & 3) * 32 + ((g >> 1) << 4);
                ldsm_x4(qa[ds][hh][0], qa[ds][hh][1], qa[ds][hh][2], qa[ds][hh][3],
                        sQ + (uint32_t)((ds >> 2)*16384) + SWZ128((uint32_t)(row*128 + byo)));
            }

        float m[2][2], l[2][2], oa[2][8][4] = {};
        #pragma unroll
        for (int hh = 0; hh < 2; hh++) { m[hh][0] = m[hh][1] = -1e30f; l[hh][0] = l[hh][1] = 0.f; }

        for (int kt = 0; kt <= kt_max; kt++) {
            const uint32_t kbuf = (uint32_t)((kt & 1) * 16384);
            CP_WAIT(0);
            __syncthreads();
            if (kt < kt_max) load_kv(kt + 1);
            CP_COMMIT();

            const bool need_mask = (kt >= 2 * qt);
            #pragma unroll
            for (int hh = 0; hh < 2; hh++) {
                float sacc[8][4] = {};
                #pragma unroll
                for (int ds = 0; ds < 8; ds++) {
                    uint32_t b[16];
                    #pragma unroll
                    for (int nb = 0; nb < 4; nb++) {
                        int row = nb*16 + ((g >> 1) << 3) + l7;
                        int byo = (ds & 3)*32 + ((g & 1) << 4);
                        ldsm_x4(b[nb*4+0], b[nb*4+1], b[nb*4+2], b[nb*4+3],
                                sK + kbuf + (uint32_t)((ds >> 2)*8192)
                                   + SWZ128((uint32_t)(row*128 + byo)));
                    }
                    #pragma unroll
                    for (int ni = 0; ni < 8; ni++)
                        mma_tf32(sacc[ni], qa[ds][hh], b[(ni>>1)*4 + (ni&1)*2],
                                                       b[(ni>>1)*4 + (ni&1)*2 + 1]);
                }

                const int rg0 = q0 + mw + hh*16 + r_loc;   // global q rows
                const int rg1 = rg0 + 8;
                if (need_mask) {
                    #pragma unroll
                    for (int ni = 0; ni < 8; ni++) {
                        int cg = kt*64 + ni*8 + ec;
                        if (cg     > rg0) sacc[ni][0] = -1e30f;
                        if (cg + 1 > rg0) sacc[ni][1] = -1e30f;
                        if (cg     > rg1) sacc[ni][2] = -1e30f;
                        if (cg + 1 > rg1) sacc[ni][3] = -1e30f;
                    }
                }

                float rx0 = -1e30f, rx1 = -1e30f;
                #pragma unroll
                for (int ni = 0; ni < 8; ni++) {
                    rx0 = fmaxf(rx0, fmaxf(sacc[ni][0], sacc[ni][1]));
                    rx1 = fmaxf(rx1, fmaxf(sacc[ni][2], sacc[ni][3]));
                }
                rx0 = fmaxf(rx0, __shfl_xor_sync(0xffffffffu, rx0, 1));
                rx0 = fmaxf(rx0, __shfl_xor_sync(0xffffffffu, rx0, 2));
                rx1 = fmaxf(rx1, __shfl_xor_sync(0xffffffffu, rx1, 1));
                rx1 = fmaxf(rx1, __shfl_xor_sync(0xffffffffu, rx1, 2));
                float mn0 = fmaxf(m[hh][0], rx0), mn1 = fmaxf(m[hh][1], rx1);
                float c0 = __expf(m[hh][0] - mn0), c1 = __expf(m[hh][1] - mn1);
                float su0 = 0.f, su1 = 0.f;
                #pragma unroll
                for (int ni = 0; ni < 8; ni++) {
                    sacc[ni][0] = __expf(sacc[ni][0] - mn0);
                    sacc[ni][1] = __expf(sacc[ni][1] - mn0);
                    sacc[ni][2] = __expf(sacc[ni][2] - mn1);
                    sacc[ni][3] = __expf(sacc[ni][3] - mn1);
                    su0 += sacc[ni][0] + sacc[ni][1];
                    su1 += sacc[ni][2] + sacc[ni][3];
                }
                su0 += __shfl_xor_sync(0xffffffffu, su0, 1);
                su0 += __shfl_xor_sync(0xffffffffu, su0, 2);
                su1 += __shfl_xor_sync(0xffffffffu, su1, 1);
                su1 += __shfl_xor_sync(0xffffffffu, su1, 2);
                l[hh][0] = l[hh][0] * c0 + su0;
                l[hh][1] = l[hh][1] * c1 + su1;
                m[hh][0] = mn0; m[hh][1] = mn1;
                #pragma unroll
                for (int ni = 0; ni < 8; ni++) {
                    oa[hh][ni][0] *= c0; oa[hh][ni][1] *= c0;
                    oa[hh][ni][2] *= c1; oa[hh][ni][3] *= c1;
                }

                // P -> sP (warp-private rows)
                const int row0 = mw + hh*16 + r_loc;
                #pragma unroll
                for (int ni = 0; ni < 8; ni++) {
                    int col = ni*8 + ec, ch = col >> 5, cc = col & 31;
                    float2 p0 = make_float2(to_tf32(sacc[ni][0]), to_tf32(sacc[ni][1]));
                    float2 p1 = make_float2(to_tf32(sacc[ni][2]), to_tf32(sacc[ni][3]));
                    *(float2*)(dsm + 32768 + ch*16384 + SWZ128((uint32_t)(row0*128 + cc*4))) = p0;
                    *(float2*)(dsm + 32768 + ch*16384 + SWZ128((uint32_t)((row0+8)*128 + cc*4))) = p1;
                }
            }
            __syncwarp();

            #pragma unroll
            for (int ks = 0; ks < 8; ks++) {
                uint32_t a0[4], a1[4];
                {
                    int row = mw + ((g & 1) << 3) + l7;
                    int byo = (ks & 3)*32 + ((g >> 1) << 4);
                    uint32_t base = sP + (uint32_t)((ks >> 2)*16384);
                    ldsm_x4(a0[0], a0[1], a0[2], a0[3],
                            base + SWZ128((uint32_t)(row*128 + byo)));
                    ldsm_x4(a1[0], a1[1], a1[2], a1[3],
                            base + SWZ128((uint32_t)((row + 16)*128 + byo)));
                }
                uint32_t b[16];
                #pragma unroll
                for (int nb = 0; nb < 4; nb++) {
                    int rowb = nb*16 + ((g >> 1) << 3) + l7;
                    int byob = (ks & 3)*32 + ((g & 1) << 4);
                    ldsm_x4(b[nb*4+0], b[nb*4+1], b[nb*4+2], b[nb*4+3],
                            sV + kbuf + (uint32_t)((ks >> 2)*8192)
                               + SWZ128((uint32_t)(rowb*128 + byob)));
                }
                #pragma unroll
                for (int ni = 0; ni < 8; ni++) {
                    mma_tf32(oa[0][ni], a0, b[(ni>>1)*4 + (ni&1)*2],
                                            b[(ni>>1)*4 + (ni&1)*2 + 1]);
                    mma_tf32(oa[1][ni], a1, b[(ni>>1)*4 + (ni&1)*2],
                                            b[(ni>>1)*4 + (ni&1)*2 + 1]);
                }
            }
        }

        #pragma unroll
        for (int hh = 0; hh < 2; hh++) {
            float inv0 = 1.f / l[hh][0], inv1 = 1.f / l[hh][1];
            int row0 = q0 + mw + hh*16 + r_loc;
            #pragma unroll
            for (int ni = 0; ni < 8; ni++) {
                int e = ni*8 + ec;
                *(float2*)&g_z[((size_t)h*SQ + row0    ) * DH + e] =
                    make_float2(to_tf32(oa[hh][ni][0]*inv0), to_tf32(oa[hh][ni][1]*inv0));
                *(float2*)&g_z[((size_t)h*SQ + row0 + 8) * DH + e] =
                    make_float2(to_tf32(oa[hh][ni][2]*inv1), to_tf32(oa[hh][ni][3]*inv1));
            }
        }
    }
}

// ---------------- Output projection, persistent over d-tiles --------------------
// grid (16 s, 16 h), 256 threads. dyn smem: Z @0 (32KB), W @32768 (3x32KB) = 128KB
__global__ __launch_bounds__(256, 1) void outproj_mma_kernel(
    const float* __restrict__ bO, float* __restrict__ out)
{
    extern __shared__ uint8_t dsm[];
    const uint32_t sZ = smem_u32(dsm);
    const uint32_t sW = sZ + 32768;

    const int tid = threadIdx.x, w = tid >> 5, lane = tid & 31;
    const int s0 = blockIdx.x * 128, h = blockIdx.y;
    const float* WOT = g_wot + (size_t)h * DM * DH;

    const int mw = w * 16;
    const int g  = lane >> 3, l7 = lane & 7;

    auto prefetch_w = [&](int d) {
        const int d0 = d * 128;
        const uint32_t base = sW + (uint32_t)((d % 3) * 32768);
        #pragma unroll
        for (int i = 0; i < 8; i++) {
            int idx = tid + i * 256, r = idx >> 4, q = idx & 15;
            uint32_t off = (uint32_t)((q>>3)*16384) + SWZ128((uint32_t)(r*128 + (q&7)*16));
            CP_ASYNC16(base + off, &WOT[(size_t)(d0 + r) * DH + q*4]);
        }
    };

    // Z tile once
    #pragma unroll
    for (int i = 0; i < 8; i++) {
        int idx = tid + i * 256, r = idx >> 4, q = idx & 15;
        uint32_t off = (uint32_t)((q>>3)*16384) + SWZ128((uint32_t)(r*128 + (q&7)*16));
        CP_ASYNC16(sZ + off, &g_z[((size_t)h*SQ + s0 + r) * DH + q*4]);
    }
    prefetch_w(0);
    CP_COMMIT();           // G0: Z + W0
    prefetch_w(1);
    CP_COMMIT();           // G1: W1

    const int r0 = mw + (lane >> 2);
    const int ec = (lane & 3) * 2;

    #pragma unroll 1
    for (int d = 0; d < 8; d++) {
        CP_WAIT(1);
        __syncthreads();
        if (d + 2 < 8) prefetch_w(d + 2);
        CP_COMMIT();

        const uint32_t sbW = sW + (uint32_t)((d % 3) * 32768);
        float acc[16][4] = {};

        #pragma unroll
        for (int ks = 0; ks < 8; ks++) {
            uint32_t a[4];
            {
                int row = mw + ((g & 1) << 3) + l7;
                int byo = (ks & 3)*32 + ((g >> 1) << 4);
                ldsm_x4(a[0], a[1], a[2], a[3],
                        sZ + (uint32_t)((ks >> 2)*16384) + SWZ128((uint32_t)(row*128 + byo)));
            }
            uint32_t b[32];
            #pragma unroll
            for (int nb = 0; nb < 8; nb++) {
                int row = nb * 16 + ((g >> 1) << 3) + l7;
                int byo = (ks & 3)*32 + ((g & 1) << 4);
                ldsm_x4(b[nb*4+0], b[nb*4+1], b[nb*4+2], b[nb*4+3],
                        sbW + (uint32_t)((ks >> 2)*16384) + SWZ128((uint32_t)(row*128 + byo)));
            }
            #pragma unroll
            for (int ni = 0; ni < 16; ni++)
                mma_tf32(acc[ni], a, b[(ni >> 1)*4 + (ni & 1)*2],
                                     b[(ni >> 1)*4 + (ni & 1)*2 + 1]);
        }

        const int d0 = d * 128;
        #pragma unroll
        for (int ni = 0; ni < 16; ni++) {
            int dg = d0 + ni*8 + ec;
            float b0 = bO[dg] * 0.0625f, b1 = bO[dg + 1] * 0.0625f;
            int sg0 = s0 + r0, sg1 = sg0 + 8;
            *(float2*)&out[((size_t)sg0 * NH + h) * DM + dg] =
                make_float2(acc[ni][0] + b0, acc[ni][1] + b1);
            *(float2*)&out[((size_t)sg1 * NH + h) * DM + dg] =
                make_float2(acc[ni][2] + b0, acc[ni][3] + b1);
        }
    }
}

// -------------------------------------------------------------------------------
extern "C" void kernel_launch(void* const* d_in, const int* in_sizes, int n_in,
                              void* d_out, int out_size)
{
    (void)in_sizes; (void)n_in; (void)out_size;
    const float* xq = (const float*)d_in[0];
    const float* xk = (const float*)d_in[1];
    const float* xv = (const float*)d_in[2];
    const float* WQ = (const float*)d_in[3];
    const float* bQ = (const float*)d_in[4];
    const float* WK = (const float*)d_in[5];
    const float* bK = (const float*)d_in[6];
    const float* WV = (const float*)d_in[7];
    const float* bV = (const float*)d_in[8];
    const float* WO = (const float*)d_in[9];
    const float* bO = (const float*)d_in[10];
    float* out = (float*)d_out;

    static int smem_set = 0;
    if (!smem_set) {
        cudaFuncSetAttribute(attn_mma_kernel,
                             cudaFuncAttributeMaxDynamicSharedMemorySize, 131072);
        cudaFuncSetAttribute(proj_mma_kernel,
                             cudaFuncAttributeMaxDynamicSharedMemorySize, 73728);
        cudaFuncSetAttribute(outproj_mma_kernel,
                             cudaFuncAttributeMaxDynamicSharedMemorySize, 131072);
        smem_set = 1;
    }

    transpose_w_kernel<<<dim3(64, 64), dim3(32, 8)>>>(WQ, WK, WV, WO);
    proj_mma_kernel<<<dim3(16, 16, 3), 256, 73728>>>(xq, xk, xv, bQ, bK, bV);
    vtrans_kernel<<<dim3(64, 2, 16), dim3(32, 8)>>>();
    attn_mma_kernel<<<dim3(8, 16), 128, 131072>>>();
    outproj_mma_kernel<<<dim3(16, 16), 256, 131072>>>(bO, out);
}

// round 9
// speedup vs baseline: 1.0641x; 1.0641x over previous
#include <cuda_runtime.h>
#include <cstdint>
#include <math.h>

#define SQ 2048
#define NH 16
#define DM 1024
#define DH 64

__device__ float g_q[NH * SQ * DH];       // pre-scaled by 1/8, tf32-rounded
__device__ float g_k[NH * SQ * DH];
__device__ float g_v[NH * SQ * DH];
__device__ float g_vt[NH * DH * SQ];      // V^T: [h][e][s], tf32-rounded
__device__ float g_z[NH * SQ * DH];
__device__ float g_wt[3][NH * DH * DM];   // W^T, tf32-rounded
__device__ float g_wot[NH * DM * DH];     // W_O^T, tf32-rounded

__device__ __forceinline__ uint32_t smem_u32(const void* p) {
    uint32_t a;
    asm("{ .reg .u64 t; cvta.to.shared.u64 t, %1; cvt.u32.u64 %0, t; }" : "=r"(a) : "l"(p));
    return a;
}
#define SWZ128(x) ((x) ^ (((x) >> 3) & 0x70))

__device__ __forceinline__ float to_tf32(float x) {
    float y;
    asm("cvt.rna.tf32.f32 %0, %1;" : "=f"(y) : "f"(x));
    return y;
}
__device__ __forceinline__ void ldsm_x4(uint32_t& r0, uint32_t& r1, uint32_t& r2,
                                        uint32_t& r3, uint32_t addr) {
    asm volatile("ldmatrix.sync.aligned.m8n8.x4.shared.b16 {%0,%1,%2,%3}, [%4];"
                 : "=r"(r0), "=r"(r1), "=r"(r2), "=r"(r3) : "r"(addr));
}
__device__ __forceinline__ void mma_tf32(float* c, const uint32_t* a,
                                         uint32_t b0, uint32_t b1) {
    asm volatile(
        "mma.sync.aligned.m16n8k8.row.col.f32.tf32.tf32.f32 "
        "{%0,%1,%2,%3}, {%4,%5,%6,%7}, {%8,%9}, {%0,%1,%2,%3};"
        : "+f"(c[0]), "+f"(c[1]), "+f"(c[2]), "+f"(c[3])
        : "r"(a[0]), "r"(a[1]), "r"(a[2]), "r"(a[3]), "r"(b0), "r"(b1));
}
#define CP_ASYNC16(dst, src) \
    asm volatile("cp.async.cg.shared.global [%0], [%1], 16;" :: "r"(dst), "l"(src))
#define CP_COMMIT() asm volatile("cp.async.commit_group;" ::: "memory")
#define CP_WAIT(n)  asm volatile("cp.async.wait_group %0;" :: "n"(n) : "memory")

// ---------------- W transpose (+tf32 round) -----------------------------------
__global__ void transpose_w_kernel(const float* __restrict__ WQ, const float* __restrict__ WK,
                                   const float* __restrict__ WV, const float* __restrict__ WO)
{
    __shared__ float t[32][33];
    const int m = blockIdx.y >> 4, h = blockIdx.y & 15;
    const float* src; float* dst; int R, C;
    if (m == 0)      { src = WQ + (size_t)h*DM*DH; dst = g_wt[0] + (size_t)h*DH*DM; R = DM; C = DH; }
    else if (m == 1) { src = WK + (size_t)h*DM*DH; dst = g_wt[1] + (size_t)h*DH*DM; R = DM; C = DH; }
    else if (m == 2) { src = WV + (size_t)h*DM*DH; dst = g_wt[2] + (size_t)h*DH*DM; R = DM; C = DH; }
    else             { src = WO + (size_t)h*DH*DM; dst = g_wot   + (size_t)h*DM*DH; R = DH; C = DM; }
    const int nrt = R / 32, rt = blockIdx.x % nrt, ct = blockIdx.x / nrt;
    const int x = ct * 32 + threadIdx.x;
    #pragma unroll
    for (int j = 0; j < 4; j++)
        t[threadIdx.y + j*8][threadIdx.x] =
            to_tf32(src[(size_t)(rt*32 + threadIdx.y + j*8) * C + x]);
    __syncthreads();
    const int xo = rt * 32 + threadIdx.x;
    #pragma unroll
    for (int j = 0; j < 4; j++)
        dst[(size_t)(ct*32 + threadIdx.y + j*8) * R + xo] = t[threadIdx.x][threadIdx.y + j*8];
}

// ---------------- V transpose: g_v [h][s][e] -> g_vt [h][e][s] -----------------
__global__ void vtrans_kernel()
{
    __shared__ float t[32][33];
    const int h = blockIdx.z;
    const int s0 = blockIdx.x * 32, e0 = blockIdx.y * 32;
    #pragma unroll
    for (int j = 0; j < 4; j++)
        t[threadIdx.y + j*8][threadIdx.x] =
            g_v[((size_t)h*SQ + s0 + threadIdx.y + j*8) * DH + e0 + threadIdx.x];
    __syncthreads();
    #pragma unroll
    for (int j = 0; j < 4; j++)
        g_vt[((size_t)h*DH + e0 + threadIdx.y + j*8) * SQ + s0 + threadIdx.x] =
            t[threadIdx.x][threadIdx.y + j*8];
}

// ---------------- Projection via HMMA tf32, 4-stage cp.async -------------------
// dyn smem: A stages @ 0 + i*16K (64KB), B stages @ 65536 + i*8K (32KB) = 98304B
__global__ __launch_bounds__(256, 1) void proj_mma_kernel(
    const float* __restrict__ xq, const float* __restrict__ xk, const float* __restrict__ xv,
    const float* __restrict__ bQ, const float* __restrict__ bK, const float* __restrict__ bV)
{
    extern __shared__ uint8_t dsm[];
    const uint32_t sA = smem_u32(dsm);
    const uint32_t sB = sA + 65536;

    const int tid = threadIdx.x, w = tid >> 5, lane = tid & 31;
    const int h = blockIdx.y, which = blockIdx.z;
    const int s0 = blockIdx.x * 128;

    const float* X    = (which == 0) ? xq : (which == 1) ? xk : xv;
    const float* bias = (which == 0) ? bQ : (which == 1) ? bK : bV;
    const float* WT   = g_wt[which] + (size_t)h * DH * DM;
    float* out        = (which == 0) ? g_q : (which == 1) ? g_k : g_v;

    const int mw = w * 16;
    const int g  = lane >> 3, l7 = lane & 7;

    auto prefetch = [&](int c) {
        const int k0 = c * 32;
        const uint32_t ab = sA + (uint32_t)((c & 3) * 16384);
        const uint32_t bb = sB + (uint32_t)((c & 3) * 8192);
        #pragma unroll
        for (int i = 0; i < 4; i++) {
            int idx = tid + i * 256, r = idx >> 3, q = idx & 7;
            CP_ASYNC16(ab + SWZ128((uint32_t)(r*128 + q*16)),
                       &X[(((size_t)(s0 + r)) * NH + h) * DM + k0 + q*4]);
        }
        #pragma unroll
        for (int i = 0; i < 2; i++) {
            int idx = tid + i * 256, n = idx >> 3, q = idx & 7;
            CP_ASYNC16(bb + SWZ128((uint32_t)(n*128 + q*16)),
                       &WT[(size_t)n * DM + k0 + q*4]);
        }
    };

    float acc[8][4] = {};

    prefetch(0); CP_COMMIT();
    prefetch(1); CP_COMMIT();
    prefetch(2); CP_COMMIT();

    #pragma unroll 1
    for (int c = 0; c < 32; c++) {
        CP_WAIT(2);
        __syncthreads();
        if (c + 3 < 32) prefetch(c + 3);
        CP_COMMIT();

        const uint32_t sbA = sA + (uint32_t)((c & 3) * 16384);
        const uint32_t sbB = sB + (uint32_t)((c & 3) * 8192);
        #pragma unroll
        for (int kk = 0; kk < 4; kk++) {
            const int kb = kk * 32;
            uint32_t a[4];
            {
                int row = mw + ((g & 1) << 3) + l7;
                int byo = kb + ((g >> 1) << 4);
                ldsm_x4(a[0], a[1], a[2], a[3], sbA + SWZ128((uint32_t)(row*128 + byo)));
            }
            uint32_t b[16];
            #pragma unroll
            for (int nb = 0; nb < 4; nb++) {
                int row = nb * 16 + ((g >> 1) << 3) + l7;
                int byo = kb + ((g & 1) << 4);
                ldsm_x4(b[nb*4+0], b[nb*4+1], b[nb*4+2], b[nb*4+3],
                        sbB + SWZ128((uint32_t)(row*128 + byo)));
            }
            #pragma unroll
            for (int ni = 0; ni < 8; ni++)
                mma_tf32(acc[ni], a, b[(ni >> 1)*4 + (ni & 1)*2],
                                     b[(ni >> 1)*4 + (ni & 1)*2 + 1]);
        }
    }

    const int r0 = mw + (lane >> 2);
    const int ec = (lane & 3) * 2;

    #pragma unroll
    for (int ni = 0; ni < 8; ni++) {
        float bv0 = bias[h * DH + ni*8 + ec];
        float bv1 = bias[h * DH + ni*8 + ec + 1];
        acc[ni][0] += bv0; acc[ni][1] += bv1;
        acc[ni][2] += bv0; acc[ni][3] += bv1;
    }

    if (which < 2) {
        const float L2B = 0.41524101186092029f;
        #pragma unroll
        for (int ni = 0; ni < 4; ni++) {
            #pragma unroll
            for (int cc = 0; cc < 2; cc++) {
                int j = ni*8 + ec + cc;
                float invf = exp2f(-(float)j * L2B);
                #pragma unroll
                for (int rr = 0; rr < 2; rr++) {
                    float pos = (float)(s0 + r0 + rr*8);
                    float sn, cs; sincosf(pos * invf, &sn, &cs);
                    int ci = rr*2 + cc;
                    float x = acc[ni][ci], y = acc[ni+4][ci];
                    acc[ni][ci]   = x*cs - y*sn;
                    acc[ni+4][ci] = y*cs + x*sn;
                }
            }
        }
    }

    const float osc = (which == 0) ? 0.125f : 1.0f;   // fold attention scale into Q
    #pragma unroll
    for (int ni = 0; ni < 8; ni++) {
        int e = ni*8 + ec;
        *(float2*)&out[((size_t)h*SQ + s0 + r0    ) * DH + e] =
            make_float2(to_tf32(acc[ni][0]*osc), to_tf32(acc[ni][1]*osc));
        *(float2*)&out[((size_t)h*SQ + s0 + r0 + 8) * DH + e] =
            make_float2(to_tf32(acc[ni][2]*osc), to_tf32(acc[ni][3]*osc));
    }
}

// ---------------- Attention via HMMA tf32, cp.async double-buffered ------------
// dynamic smem: Q/P @0 (16KB), K @16384 (2x16KB), V @49152 (2x16KB) = 80KB
__global__ __launch_bounds__(128, 2) void attn_mma_kernel()
{
    extern __shared__ uint8_t dsm[];
    const uint32_t sQ = smem_u32(dsm);
    const uint32_t sK = sQ + 16384;
    const uint32_t sV = sQ + 49152;

    const int tid = threadIdx.x, w = tid >> 5, lane = tid & 31;
    const int h = blockIdx.y;
    const int g = lane >> 3, l7 = lane & 7;
    const int mw = w * 16;
    const int r_loc = lane >> 2, ec = (lane & 3) * 2;

    for (int rep = 0; rep < 2; rep++) {
        const int qb = rep ? (31 - (int)blockIdx.x) : (int)blockIdx.x;
        const int q0 = qb * 64;

        __syncthreads();
        #pragma unroll
        for (int i = 0; i < 8; i++) {
            int idx = tid + i * 128, r = idx >> 4, q = idx & 15;
            uint32_t off = (uint32_t)((q>>3)*8192) + SWZ128((uint32_t)(r*128 + (q&7)*16));
            CP_ASYNC16(sQ + off, &g_q[((size_t)h*SQ + q0 + r) * DH + q*4]);
        }
        CP_COMMIT();
        #pragma unroll
        for (int i = 0; i < 8; i++) {
            int idx = tid + i * 128, r = idx >> 4, q = idx & 15;
            uint32_t off = (uint32_t)((q>>3)*8192) + SWZ128((uint32_t)(r*128 + (q&7)*16));
            CP_ASYNC16(sK + off, &g_k [((size_t)h*SQ + r) * DH + q*4]);
            CP_ASYNC16(sV + off, &g_vt[((size_t)h*DH + r) * SQ + q*4]);
        }
        CP_COMMIT();
        CP_WAIT(1);
        __syncthreads();

        uint32_t qa[8][4];
        #pragma unroll
        for (int ds = 0; ds < 8; ds++) {
            int row = mw + ((g & 1) << 3) + l7;
            int byo = (ds & 3) * 32 + ((g >> 1) << 4);
            ldsm_x4(qa[ds][0], qa[ds][1], qa[ds][2], qa[ds][3],
                    sQ + (uint32_t)((ds >> 2)*8192) + SWZ128((uint32_t)(row*128 + byo)));
        }

        float m0 = -1e30f, m1 = -1e30f, l0 = 0.f, l1 = 0.f;
        float oa[8][4] = {};

        for (int kt = 0; kt <= qb; kt++) {
            const uint32_t kb_off = (uint32_t)((kt & 1) * 16384);
            CP_WAIT(0);
            __syncthreads();
            if (kt < qb) {
                const int kk0 = (kt + 1) * 64;
                const uint32_t nb_off = (uint32_t)(((kt + 1) & 1) * 16384);
                #pragma unroll
                for (int i = 0; i < 8; i++) {
                    int idx = tid + i * 128, r = idx >> 4, q = idx & 15;
                    uint32_t off = nb_off + (uint32_t)((q>>3)*8192)
                                 + SWZ128((uint32_t)(r*128 + (q&7)*16));
                    CP_ASYNC16(sK + off, &g_k [((size_t)h*SQ + kk0 + r) * DH + q*4]);
                    CP_ASYNC16(sV + off, &g_vt[((size_t)h*DH + r) * SQ + kk0 + q*4]);
                }
                CP_COMMIT();
            }

            float sacc[8][4] = {};
            #pragma unroll
            for (int ds = 0; ds < 8; ds++) {
                uint32_t b[16];
                #pragma unroll
                for (int nb = 0; nb < 4; nb++) {
                    int row = nb*16 + ((g >> 1) << 3) + l7;
                    int byo = (ds & 3)*32 + ((g & 1) << 4);
                    ldsm_x4(b[nb*4+0], b[nb*4+1], b[nb*4+2], b[nb*4+3],
                            sK + kb_off + (uint32_t)((ds >> 2)*8192)
                               + SWZ128((uint32_t)(row*128 + byo)));
                }
                #pragma unroll
                for (int ni = 0; ni < 8; ni++)
                    mma_tf32(sacc[ni], qa[ds], b[(ni>>1)*4 + (ni&1)*2],
                                               b[(ni>>1)*4 + (ni&1)*2 + 1]);
            }

            const bool diag = (kt == qb);
            if (diag) {
                #pragma unroll
                for (int ni = 0; ni < 8; ni++) {
                    int col = ni*8 + ec;
                    int row0 = mw + r_loc, row1 = row0 + 8;
                    if (col     > row0) sacc[ni][0] = -1e30f;
                    if (col + 1 > row0) sacc[ni][1] = -1e30f;
                    if (col     > row1) sacc[ni][2] = -1e30f;
                    if (col + 1 > row1) sacc[ni][3] = -1e30f;
                }
            }

            float rx0 = -1e30f, rx1 = -1e30f;
            #pragma unroll
            for (int ni = 0; ni < 8; ni++) {
                rx0 = fmaxf(rx0, fmaxf(sacc[ni][0], sacc[ni][1]));
                rx1 = fmaxf(rx1, fmaxf(sacc[ni][2], sacc[ni][3]));
            }
            rx0 = fmaxf(rx0, __shfl_xor_sync(0xffffffffu, rx0, 1));
            rx0 = fmaxf(rx0, __shfl_xor_sync(0xffffffffu, rx0, 2));
            rx1 = fmaxf(rx1, __shfl_xor_sync(0xffffffffu, rx1, 1));
            rx1 = fmaxf(rx1, __shfl_xor_sync(0xffffffffu, rx1, 2));
            float mn0 = fmaxf(m0, rx0), mn1 = fmaxf(m1, rx1);
            float c0 = __expf(m0 - mn0), c1 = __expf(m1 - mn1);
            float su0 = 0.f, su1 = 0.f;
            #pragma unroll
            for (int ni = 0; ni < 8; ni++) {
                sacc[ni][0] = __expf(sacc[ni][0] - mn0);
                sacc[ni][1] = __expf(sacc[ni][1] - mn0);
                sacc[ni][2] = __expf(sacc[ni][2] - mn1);
                sacc[ni][3] = __expf(sacc[ni][3] - mn1);
                su0 += sacc[ni][0] + sacc[ni][1];
                su1 += sacc[ni][2] + sacc[ni][3];
            }
            su0 += __shfl_xor_sync(0xffffffffu, su0, 1);
            su0 += __shfl_xor_sync(0xffffffffu, su0, 2);
            su1 += __shfl_xor_sync(0xffffffffu, su1, 1);
            su1 += __shfl_xor_sync(0xffffffffu, su1, 2);
            l0 = l0 * c0 + su0; l1 = l1 * c1 + su1;
            m0 = mn0; m1 = mn1;
            #pragma unroll
            for (int ni = 0; ni < 8; ni++) {
                oa[ni][0] *= c0; oa[ni][1] *= c0;
                oa[ni][2] *= c1; oa[ni][3] *= c1;
            }

            #pragma unroll
            for (int ni = 0; ni < 8; ni++) {
                int col = ni*8 + ec, ch = col >> 5, cc = col & 31;
                int row0 = mw + r_loc;
                float2 p0 = make_float2(to_tf32(sacc[ni][0]), to_tf32(sacc[ni][1]));
                float2 p1 = make_float2(to_tf32(sacc[ni][2]), to_tf32(sacc[ni][3]));
                *(float2*)(dsm + ch*8192 + SWZ128((uint32_t)(row0*128 + cc*4))) = p0;
                *(float2*)(dsm + ch*8192 + SWZ128((uint32_t)((row0+8)*128 + cc*4))) = p1;
            }
            __syncwarp();

            #pragma unroll
            for (int ks = 0; ks < 8; ks++) {
                uint32_t a[4];
                int row = mw + ((g & 1) << 3) + l7;
                int byo = (ks & 3)*32 + ((g >> 1) << 4);
                ldsm_x4(a[0], a[1], a[2], a[3],
                        sQ + (uint32_t)((ks >> 2)*8192) + SWZ128((uint32_t)(row*128 + byo)));
                uint32_t b[16];
                #pragma unroll
                for (int nb = 0; nb < 4; nb++) {
                    int rowb = nb*16 + ((g >> 1) << 3) + l7;
                    int byob = (ks & 3)*32 + ((g & 1) << 4);
                    ldsm_x4(b[nb*4+0], b[nb*4+1], b[nb*4+2], b[nb*4+3],
                            sV + kb_off + (uint32_t)((ks >> 2)*8192)
                               + SWZ128((uint32_t)(rowb*128 + byob)));
                }
                #pragma unroll
                for (int ni = 0; ni < 8; ni++)
                    mma_tf32(oa[ni], a, b[(ni>>1)*4 + (ni&1)*2],
                                        b[(ni>>1)*4 + (ni&1)*2 + 1]);
            }
        }

        float inv0 = 1.f / l0, inv1 = 1.f / l1;
        int row0 = q0 + mw + r_loc;
        #pragma unroll
        for (int ni = 0; ni < 8; ni++) {
            int e = ni*8 + ec;
            *(float2*)&g_z[((size_t)h*SQ + row0    ) * DH + e] =
                make_float2(to_tf32(oa[ni][0]*inv0), to_tf32(oa[ni][1]*inv0));
            *(float2*)&g_z[((size_t)h*SQ + row0 + 8) * DH + e] =
                make_float2(to_tf32(oa[ni][2]*inv1), to_tf32(oa[ni][3]*inv1));
        }
    }
}

// ---------------- Output projection, persistent over d-tiles --------------------
// grid (16 s, 16 h), 256 threads. dyn smem: Z @0 (32KB), W @32768 (3x32KB) = 128KB
__global__ __launch_bounds__(256, 1) void outproj_mma_kernel(
    const float* __restrict__ bO, float* __restrict__ out)
{
    extern __shared__ uint8_t dsm[];
    const uint32_t sZ = smem_u32(dsm);
    const uint32_t sW = sZ + 32768;

    const int tid = threadIdx.x, w = tid >> 5, lane = tid & 31;
    const int s0 = blockIdx.x * 128, h = blockIdx.y;
    const float* WOT = g_wot + (size_t)h * DM * DH;

    const int mw = w * 16;
    const int g  = lane >> 3, l7 = lane & 7;

    auto prefetch_w = [&](int d) {
        const int d0 = d * 128;
        const uint32_t base = sW + (uint32_t)((d % 3) * 32768);
        #pragma unroll
        for (int i = 0; i < 8; i++) {
            int idx = tid + i * 256, r = idx >> 4, q = idx & 15;
            uint32_t off = (uint32_t)((q>>3)*16384) + SWZ128((uint32_t)(r*128 + (q&7)*16));
            CP_ASYNC16(base + off, &WOT[(size_t)(d0 + r) * DH + q*4]);
        }
    };

    #pragma unroll
    for (int i = 0; i < 8; i++) {
        int idx = tid + i * 256, r = idx >> 4, q = idx & 15;
        uint32_t off = (uint32_t)((q>>3)*16384) + SWZ128((uint32_t)(r*128 + (q&7)*16));
        CP_ASYNC16(sZ + off, &g_z[((size_t)h*SQ + s0 + r) * DH + q*4]);
    }
    prefetch_w(0);
    CP_COMMIT();
    prefetch_w(1);
    CP_COMMIT();

    const int r0 = mw + (lane >> 2);
    const int ec = (lane & 3) * 2;

    #pragma unroll 1
    for (int d = 0; d < 8; d++) {
        CP_WAIT(1);
        __syncthreads();
        if (d + 2 < 8) prefetch_w(d + 2);
        CP_COMMIT();

        const uint32_t sbW = sW + (uint32_t)((d % 3) * 32768);
        float acc[16][4] = {};

        #pragma unroll
        for (int ks = 0; ks < 8; ks++) {
            uint32_t a[4];
            {
                int row = mw + ((g & 1) << 3) + l7;
                int byo = (ks & 3)*32 + ((g >> 1) << 4);
                ldsm_x4(a[0], a[1], a[2], a[3],
                        sZ + (uint32_t)((ks >> 2)*16384) + SWZ128((uint32_t)(row*128 + byo)));
            }
            uint32_t b[32];
            #pragma unroll
            for (int nb = 0; nb < 8; nb++) {
                int row = nb * 16 + ((g >> 1) << 3) + l7;
                int byo = (ks & 3)*32 + ((g & 1) << 4);
                ldsm_x4(b[nb*4+0], b[nb*4+1], b[nb*4+2], b[nb*4+3],
                        sbW + (uint32_t)((ks >> 2)*16384) + SWZ128((uint32_t)(row*128 + byo)));
            }
            #pragma unroll
            for (int ni = 0; ni < 16; ni++)
                mma_tf32(acc[ni], a, b[(ni >> 1)*4 + (ni & 1)*2],
                                     b[(ni >> 1)*4 + (ni & 1)*2 + 1]);
        }

        const int d0 = d * 128;
        #pragma unroll
        for (int ni = 0; ni < 16; ni++) {
            int dg = d0 + ni*8 + ec;
            float b0 = bO[dg] * 0.0625f, b1 = bO[dg + 1] * 0.0625f;
            int sg0 = s0 + r0, sg1 = sg0 + 8;
            *(float2*)&out[((size_t)sg0 * NH + h) * DM + dg] =
                make_float2(acc[ni][0] + b0, acc[ni][1] + b1);
            *(float2*)&out[((size_t)sg1 * NH + h) * DM + dg] =
                make_float2(acc[ni][2] + b0, acc[ni][3] + b1);
        }
    }
}

// -------------------------------------------------------------------------------
extern "C" void kernel_launch(void* const* d_in, const int* in_sizes, int n_in,
                              void* d_out, int out_size)
{
    (void)in_sizes; (void)n_in; (void)out_size;
    const float* xq = (const float*)d_in[0];
    const float* xk = (const float*)d_in[1];
    const float* xv = (const float*)d_in[2];
    const float* WQ = (const float*)d_in[3];
    const float* bQ = (const float*)d_in[4];
    const float* WK = (const float*)d_in[5];
    const float* bK = (const float*)d_in[6];
    const float* WV = (const float*)d_in[7];
    const float* bV = (const float*)d_in[8];
    const float* WO = (const float*)d_in[9];
    const float* bO = (const float*)d_in[10];
    float* out = (float*)d_out;

    static int smem_set = 0;
    if (!smem_set) {
        cudaFuncSetAttribute(attn_mma_kernel,
                             cudaFuncAttributeMaxDynamicSharedMemorySize, 81920);
        cudaFuncSetAttribute(proj_mma_kernel,
                             cudaFuncAttributeMaxDynamicSharedMemorySize, 98304);
        cudaFuncSetAttribute(outproj_mma_kernel,
                             cudaFuncAttributeMaxDynamicSharedMemorySize, 131072);
        smem_set = 1;
    }

    transpose_w_kernel<<<dim3(64, 64), dim3(32, 8)>>>(WQ, WK, WV, WO);
    proj_mma_kernel<<<dim3(16, 16, 3), 256, 98304>>>(xq, xk, xv, bQ, bK, bV);
    vtrans_kernel<<<dim3(64, 2, 16), dim3(32, 8)>>>();
    attn_mma_kernel<<<dim3(16, 16), 128, 81920>>>();
    outproj_mma_kernel<<<dim3(16, 16), 256, 131072>>>(bO, out);
}

// round 10
// speedup vs baseline: 1.0887x; 1.0231x over previous
#include <cuda_runtime.h>
#include <cstdint>
#include <math.h>

#define SQ 2048
#define NH 16
#define DM 1024
#define DH 64

__device__ float g_q[NH * SQ * DH];       // pre-scaled by log2e/8, tf32-rounded
__device__ float g_k[NH * SQ * DH];
__device__ float g_vt[NH * DH * SQ];      // V^T: [h][e][s], tf32-rounded
__device__ float g_z[NH * SQ * DH];
__device__ float g_wt[3][NH * DH * DM];   // W^T, tf32-rounded
__device__ float g_wot[NH * DM * DH];     // W_O^T, tf32-rounded
__device__ float2 g_rope[SQ * 32];        // (sin, cos) per (pos, j)

__device__ __forceinline__ uint32_t smem_u32(const void* p) {
    uint32_t a;
    asm("{ .reg .u64 t; cvta.to.shared.u64 t, %1; cvt.u32.u64 %0, t; }" : "=r"(a) : "l"(p));
    return a;
}
#define SWZ128(x) ((x) ^ (((x) >> 3) & 0x70))

__device__ __forceinline__ float to_tf32(float x) {
    float y;
    asm("cvt.rna.tf32.f32 %0, %1;" : "=f"(y) : "f"(x));
    return y;
}
__device__ __forceinline__ float ex2(float x) {
    float y;
    asm("ex2.approx.ftz.f32 %0, %1;" : "=f"(y) : "f"(x));
    return y;
}
__device__ __forceinline__ void ldsm_x4(uint32_t& r0, uint32_t& r1, uint32_t& r2,
                                        uint32_t& r3, uint32_t addr) {
    asm volatile("ldmatrix.sync.aligned.m8n8.x4.shared.b16 {%0,%1,%2,%3}, [%4];"
                 : "=r"(r0), "=r"(r1), "=r"(r2), "=r"(r3) : "r"(addr));
}
__device__ __forceinline__ void mma_tf32(float* c, const uint32_t* a,
                                         uint32_t b0, uint32_t b1) {
    asm volatile(
        "mma.sync.aligned.m16n8k8.row.col.f32.tf32.tf32.f32 "
        "{%0,%1,%2,%3}, {%4,%5,%6,%7}, {%8,%9}, {%0,%1,%2,%3};"
        : "+f"(c[0]), "+f"(c[1]), "+f"(c[2]), "+f"(c[3])
        : "r"(a[0]), "r"(a[1]), "r"(a[2]), "r"(a[3]), "r"(b0), "r"(b1));
}
#define CP_ASYNC16(dst, src) \
    asm volatile("cp.async.cg.shared.global [%0], [%1], 16;" :: "r"(dst), "l"(src))
#define CP_COMMIT() asm volatile("cp.async.commit_group;" ::: "memory")
#define CP_WAIT(n)  asm volatile("cp.async.wait_group %0;" :: "n"(n) : "memory")

// ---------------- RoPE table: (sin, cos) for pos in [0,2048), j in [0,32) ------
__global__ void rope_tab_kernel()
{
    const int idx = blockIdx.x * 256 + threadIdx.x;   // 65536 threads
    const int pos = idx >> 5, j = idx & 31;
    const float L2B = 0.41524101186092029f;           // log2(10000)/32
    float invf = exp2f(-(float)j * L2B);
    float sn, cs;
    sincosf((float)pos * invf, &sn, &cs);
    g_rope[idx] = make_float2(sn, cs);
}

// ---------------- W transpose (+tf32 round) -----------------------------------
__global__ void transpose_w_kernel(const float* __restrict__ WQ, const float* __restrict__ WK,
                                   const float* __restrict__ WV, const float* __restrict__ WO)
{
    __shared__ float t[32][33];
    const int m = blockIdx.y >> 4, h = blockIdx.y & 15;
    const float* src; float* dst; int R, C;
    if (m == 0)      { src = WQ + (size_t)h*DM*DH; dst = g_wt[0] + (size_t)h*DH*DM; R = DM; C = DH; }
    else if (m == 1) { src = WK + (size_t)h*DM*DH; dst = g_wt[1] + (size_t)h*DH*DM; R = DM; C = DH; }
    else if (m == 2) { src = WV + (size_t)h*DM*DH; dst = g_wt[2] + (size_t)h*DH*DM; R = DM; C = DH; }
    else             { src = WO + (size_t)h*DH*DM; dst = g_wot   + (size_t)h*DM*DH; R = DH; C = DM; }
    const int nrt = R / 32, rt = blockIdx.x % nrt, ct = blockIdx.x / nrt;
    const int x = ct * 32 + threadIdx.x;
    #pragma unroll
    for (int j = 0; j < 4; j++)
        t[threadIdx.y + j*8][threadIdx.x] =
            to_tf32(src[(size_t)(rt*32 + threadIdx.y + j*8) * C + x]);
    __syncthreads();
    const int xo = rt * 32 + threadIdx.x;
    #pragma unroll
    for (int j = 0; j < 4; j++)
        dst[(size_t)(ct*32 + threadIdx.y + j*8) * R + xo] = t[threadIdx.x][threadIdx.y + j*8];
}

// ---------------- Projection via HMMA tf32, 4-stage cp.async -------------------
// which==2 (V) writes transposed g_vt directly; no separate vtrans pass.
__global__ __launch_bounds__(256, 1) void proj_mma_kernel(
    const float* __restrict__ xq, const float* __restrict__ xk, const float* __restrict__ xv,
    const float* __restrict__ bQ, const float* __restrict__ bK, const float* __restrict__ bV)
{
    extern __shared__ uint8_t dsm[];
    const uint32_t sA = smem_u32(dsm);
    const uint32_t sB = sA + 65536;

    const int tid = threadIdx.x, w = tid >> 5, lane = tid & 31;
    const int h = blockIdx.y, which = blockIdx.z;
    const int s0 = blockIdx.x * 128;

    const float* X    = (which == 0) ? xq : (which == 1) ? xk : xv;
    const float* bias = (which == 0) ? bQ : (which == 1) ? bK : bV;
    const float* WT   = g_wt[which] + (size_t)h * DH * DM;

    const int mw = w * 16;
    const int g  = lane >> 3, l7 = lane & 7;

    auto prefetch = [&](int c) {
        const int k0 = c * 32;
        const uint32_t ab = sA + (uint32_t)((c & 3) * 16384);
        const uint32_t bb = sB + (uint32_t)((c & 3) * 8192);
        #pragma unroll
        for (int i = 0; i < 4; i++) {
            int idx = tid + i * 256, r = idx >> 3, q = idx & 7;
            CP_ASYNC16(ab + SWZ128((uint32_t)(r*128 + q*16)),
                       &X[(((size_t)(s0 + r)) * NH + h) * DM + k0 + q*4]);
        }
        #pragma unroll
        for (int i = 0; i < 2; i++) {
            int idx = tid + i * 256, n = idx >> 3, q = idx & 7;
            CP_ASYNC16(bb + SWZ128((uint32_t)(n*128 + q*16)),
                       &WT[(size_t)n * DM + k0 + q*4]);
        }
    };

    float acc[8][4] = {};

    prefetch(0); CP_COMMIT();
    prefetch(1); CP_COMMIT();
    prefetch(2); CP_COMMIT();

    #pragma unroll 1
    for (int c = 0; c < 32; c++) {
        CP_WAIT(2);
        __syncthreads();
        if (c + 3 < 32) prefetch(c + 3);
        CP_COMMIT();

        const uint32_t sbA = sA + (uint32_t)((c & 3) * 16384);
        const uint32_t sbB = sB + (uint32_t)((c & 3) * 8192);
        #pragma unroll
        for (int kk = 0; kk < 4; kk++) {
            const int kb = kk * 32;
            uint32_t a[4];
            {
                int row = mw + ((g & 1) << 3) + l7;
                int byo = kb + ((g >> 1) << 4);
                ldsm_x4(a[0], a[1], a[2], a[3], sbA + SWZ128((uint32_t)(row*128 + byo)));
            }
            uint32_t b[16];
            #pragma unroll
            for (int nb = 0; nb < 4; nb++) {
                int row = nb * 16 + ((g >> 1) << 3) + l7;
                int byo = kb + ((g & 1) << 4);
                ldsm_x4(b[nb*4+0], b[nb*4+1], b[nb*4+2], b[nb*4+3],
                        sbB + SWZ128((uint32_t)(row*128 + byo)));
            }
            #pragma unroll
            for (int ni = 0; ni < 8; ni++)
                mma_tf32(acc[ni], a, b[(ni >> 1)*4 + (ni & 1)*2],
                                     b[(ni >> 1)*4 + (ni & 1)*2 + 1]);
        }
    }

    const int r0 = mw + (lane >> 2);
    const int ec = (lane & 3) * 2;

    #pragma unroll
    for (int ni = 0; ni < 8; ni++) {
        float bv0 = bias[h * DH + ni*8 + ec];
        float bv1 = bias[h * DH + ni*8 + ec + 1];
        acc[ni][0] += bv0; acc[ni][1] += bv1;
        acc[ni][2] += bv0; acc[ni][3] += bv1;
    }

    if (which < 2) {
        // RoPE from precomputed table
        #pragma unroll
        for (int ni = 0; ni < 4; ni++) {
            #pragma unroll
            for (int cc = 0; cc < 2; cc++) {
                int j = ni*8 + ec + cc;
                #pragma unroll
                for (int rr = 0; rr < 2; rr++) {
                    float2 sc = g_rope[(s0 + r0 + rr*8) * 32 + j];
                    int ci = rr*2 + cc;
                    float x = acc[ni][ci], y = acc[ni+4][ci];
                    acc[ni][ci]   = x*sc.y - y*sc.x;
                    acc[ni+4][ci] = y*sc.y + x*sc.x;
                }
            }
        }
    }

    if (which == 2) {
        // write V transposed: g_vt[h][e][s]
        #pragma unroll
        for (int ni = 0; ni < 8; ni++) {
            int e = ni*8 + ec;
            int sg0 = s0 + r0, sg1 = sg0 + 8;
            g_vt[((size_t)h*DH + e    ) * SQ + sg0] = to_tf32(acc[ni][0]);
            g_vt[((size_t)h*DH + e + 1) * SQ + sg0] = to_tf32(acc[ni][1]);
            g_vt[((size_t)h*DH + e    ) * SQ + sg1] = to_tf32(acc[ni][2]);
            g_vt[((size_t)h*DH + e + 1) * SQ + sg1] = to_tf32(acc[ni][3]);
        }
    } else {
        // Q pre-scaled by log2e/8 so attention softmax can use bare ex2
        const float osc = (which == 0) ? 0.18033688011112042f : 1.0f;
        float* out = (which == 0) ? g_q : g_k;
        #pragma unroll
        for (int ni = 0; ni < 8; ni++) {
            int e = ni*8 + ec;
            *(float2*)&out[((size_t)h*SQ + s0 + r0    ) * DH + e] =
                make_float2(to_tf32(acc[ni][0]*osc), to_tf32(acc[ni][1]*osc));
            *(float2*)&out[((size_t)h*SQ + s0 + r0 + 8) * DH + e] =
                make_float2(to_tf32(acc[ni][2]*osc), to_tf32(acc[ni][3]*osc));
        }
    }
}

// ---------------- Attention via HMMA tf32, cp.async double-buffered ------------
// dynamic smem: Q/P @0 (16KB), K @16384 (2x16KB), V @49152 (2x16KB) = 80KB
__global__ __launch_bounds__(128, 2) void attn_mma_kernel()
{
    extern __shared__ uint8_t dsm[];
    const uint32_t sQ = smem_u32(dsm);
    const uint32_t sK = sQ + 16384;
    const uint32_t sV = sQ + 49152;

    const int tid = threadIdx.x, w = tid >> 5, lane = tid & 31;
    const int h = blockIdx.y;
    const int g = lane >> 3, l7 = lane & 7;
    const int mw = w * 16;
    const int r_loc = lane >> 2, ec = (lane & 3) * 2;

    for (int rep = 0; rep < 2; rep++) {
        const int qb = rep ? (31 - (int)blockIdx.x) : (int)blockIdx.x;
        const int q0 = qb * 64;

        __syncthreads();
        #pragma unroll
        for (int i = 0; i < 8; i++) {
            int idx = tid + i * 128, r = idx >> 4, q = idx & 15;
            uint32_t off = (uint32_t)((q>>3)*8192) + SWZ128((uint32_t)(r*128 + (q&7)*16));
            CP_ASYNC16(sQ + off, &g_q[((size_t)h*SQ + q0 + r) * DH + q*4]);
        }
        CP_COMMIT();
        #pragma unroll
        for (int i = 0; i < 8; i++) {
            int idx = tid + i * 128, r = idx >> 4, q = idx & 15;
            uint32_t off = (uint32_t)((q>>3)*8192) + SWZ128((uint32_t)(r*128 + (q&7)*16));
            CP_ASYNC16(sK + off, &g_k [((size_t)h*SQ + r) * DH + q*4]);
            CP_ASYNC16(sV + off, &g_vt[((size_t)h*DH + r) * SQ + q*4]);
        }
        CP_COMMIT();
        CP_WAIT(1);
        __syncthreads();

        uint32_t qa[8][4];
        #pragma unroll
        for (int ds = 0; ds < 8; ds++) {
            int row = mw + ((g & 1) << 3) + l7;
            int byo = (ds & 3) * 32 + ((g >> 1) << 4);
            ldsm_x4(qa[ds][0], qa[ds][1], qa[ds][2], qa[ds][3],
                    sQ + (uint32_t)((ds >> 2)*8192) + SWZ128((uint32_t)(row*128 + byo)));
        }

        float m0 = -1e30f, m1 = -1e30f, l0 = 0.f, l1 = 0.f;
        float oa[8][4] = {};

        for (int kt = 0; kt <= qb; kt++) {
            const uint32_t kb_off = (uint32_t)((kt & 1) * 16384);
            CP_WAIT(0);
            __syncthreads();
            if (kt < qb) {
                const int kk0 = (kt + 1) * 64;
                const uint32_t nb_off = (uint32_t)(((kt + 1) & 1) * 16384);
                #pragma unroll
                for (int i = 0; i < 8; i++) {
                    int idx = tid + i * 128, r = idx >> 4, q = idx & 15;
                    uint32_t off = nb_off + (uint32_t)((q>>3)*8192)
                                 + SWZ128((uint32_t)(r*128 + (q&7)*16));
                    CP_ASYNC16(sK + off, &g_k [((size_t)h*SQ + kk0 + r) * DH + q*4]);
                    CP_ASYNC16(sV + off, &g_vt[((size_t)h*DH + r) * SQ + kk0 + q*4]);
                }
                CP_COMMIT();
            }

            float sacc[8][4] = {};
            #pragma unroll
            for (int ds = 0; ds < 8; ds++) {
                uint32_t b[16];
                #pragma unroll
                for (int nb = 0; nb < 4; nb++) {
                    int row = nb*16 + ((g >> 1) << 3) + l7;
                    int byo = (ds & 3)*32 + ((g & 1) << 4);
                    ldsm_x4(b[nb*4+0], b[nb*4+1], b[nb*4+2], b[nb*4+3],
                            sK + kb_off + (uint32_t)((ds >> 2)*8192)
                               + SWZ128((uint32_t)(row*128 + byo)));
                }
                #pragma unroll
                for (int ni = 0; ni < 8; ni++)
                    mma_tf32(sacc[ni], qa[ds], b[(ni>>1)*4 + (ni&1)*2],
                                               b[(ni>>1)*4 + (ni&1)*2 + 1]);
            }

            const bool diag = (kt == qb);
            if (diag) {
                #pragma unroll
                for (int ni = 0; ni < 8; ni++) {
                    int col = ni*8 + ec;
                    int row0 = mw + r_loc, row1 = row0 + 8;
                    if (col     > row0) sacc[ni][0] = -1e30f;
                    if (col + 1 > row0) sacc[ni][1] = -1e30f;
                    if (col     > row1) sacc[ni][2] = -1e30f;
                    if (col + 1 > row1) sacc[ni][3] = -1e30f;
                }
            }

            float rx0 = -1e30f, rx1 = -1e30f;
            #pragma unroll
            for (int ni = 0; ni < 8; ni++) {
                rx0 = fmaxf(rx0, fmaxf(sacc[ni][0], sacc[ni][1]));
                rx1 = fmaxf(rx1, fmaxf(sacc[ni][2], sacc[ni][3]));
            }
            rx0 = fmaxf(rx0, __shfl_xor_sync(0xffffffffu, rx0, 1));
            rx0 = fmaxf(rx0, __shfl_xor_sync(0xffffffffu, rx0, 2));
            rx1 = fmaxf(rx1, __shfl_xor_sync(0xffffffffu, rx1, 1));
            rx1 = fmaxf(rx1, __shfl_xor_sync(0xffffffffu, rx1, 2));
            float mn0 = fmaxf(m0, rx0), mn1 = fmaxf(m1, rx1);
            float c0 = ex2(m0 - mn0), c1 = ex2(m1 - mn1);
            float su0 = 0.f, su1 = 0.f;
            #pragma unroll
            for (int ni = 0; ni < 8; ni++) {
                sacc[ni][0] = ex2(sacc[ni][0] - mn0);
                sacc[ni][1] = ex2(sacc[ni][1] - mn0);
                sacc[ni][2] = ex2(sacc[ni][2] - mn1);
                sacc[ni][3] = ex2(sacc[ni][3] - mn1);
                su0 += sacc[ni][0] + sacc[ni][1];
                su1 += sacc[ni][2] + sacc[ni][3];
            }
            su0 += __shfl_xor_sync(0xffffffffu, su0, 1);
            su0 += __shfl_xor_sync(0xffffffffu, su0, 2);
            su1 += __shfl_xor_sync(0xffffffffu, su1, 1);
            su1 += __shfl_xor_sync(0xffffffffu, su1, 2);
            l0 = l0 * c0 + su0; l1 = l1 * c1 + su1;
            m0 = mn0; m1 = mn1;
            #pragma unroll
            for (int ni = 0; ni < 8; ni++) {
                oa[ni][0] *= c0; oa[ni][1] *= c0;
                oa[ni][2] *= c1; oa[ni][3] *= c1;
            }

            #pragma unroll
            for (int ni = 0; ni < 8; ni++) {
                int col = ni*8 + ec, ch = col >> 5, cc = col & 31;
                int row0 = mw + r_loc;
                float2 p0 = make_float2(to_tf32(sacc[ni][0]), to_tf32(sacc[ni][1]));
                float2 p1 = make_float2(to_tf32(sacc[ni][2]), to_tf32(sacc[ni][3]));
                *(float2*)(dsm + ch*8192 + SWZ128((uint32_t)(row0*128 + cc*4))) = p0;
                *(float2*)(dsm + ch*8192 + SWZ128((uint32_t)((row0+8)*128 + cc*4))) = p1;
            }
            __syncwarp();

            #pragma unroll
            for (int ks = 0; ks < 8; ks++) {
                uint32_t a[4];
                int row = mw + ((g & 1) << 3) + l7;
                int byo = (ks & 3)*32 + ((g >> 1) << 4);
                ldsm_x4(a[0], a[1], a[2], a[3],
                        sQ + (uint32_t)((ks >> 2)*8192) + SWZ128((uint32_t)(row*128 + byo)));
                uint32_t b[16];
                #pragma unroll
                for (int nb = 0; nb < 4; nb++) {
                    int rowb = nb*16 + ((g >> 1) << 3) + l7;
                    int byob = (ks & 3)*32 + ((g & 1) << 4);
                    ldsm_x4(b[nb*4+0], b[nb*4+1], b[nb*4+2], b[nb*4+3],
                            sV + kb_off + (uint32_t)((ks >> 2)*8192)
                               + SWZ128((uint32_t)(rowb*128 + byob)));
                }
                #pragma unroll
                for (int ni = 0; ni < 8; ni++)
                    mma_tf32(oa[ni], a, b[(ni>>1)*4 + (ni&1)*2],
                                        b[(ni>>1)*4 + (ni&1)*2 + 1]);
            }
        }

        float inv0 = 1.f / l0, inv1 = 1.f / l1;
        int row0 = q0 + mw + r_loc;
        #pragma unroll
        for (int ni = 0; ni < 8; ni++) {
            int e = ni*8 + ec;
            *(float2*)&g_z[((size_t)h*SQ + row0    ) * DH + e] =
                make_float2(to_tf32(oa[ni][0]*inv0), to_tf32(oa[ni][1]*inv0));
            *(float2*)&g_z[((size_t)h*SQ + row0 + 8) * DH + e] =
                make_float2(to_tf32(oa[ni][2]*inv1), to_tf32(oa[ni][3]*inv1));
        }
    }
}

// ---------------- Output projection, persistent over d-tiles --------------------
__global__ __launch_bounds__(256, 1) void outproj_mma_kernel(
    const float* __restrict__ bO, float* __restrict__ out)
{
    extern __shared__ uint8_t dsm[];
    const uint32_t sZ = smem_u32(dsm);
    const uint32_t sW = sZ + 32768;

    const int tid = threadIdx.x, w = tid >> 5, lane = tid & 31;
    const int s0 = blockIdx.x * 128, h = blockIdx.y;
    const float* WOT = g_wot + (size_t)h * DM * DH;

    const int mw = w * 16;
    const int g  = lane >> 3, l7 = lane & 7;

    auto prefetch_w = [&](int d) {
        const int d0 = d * 128;
        const uint32_t base = sW + (uint32_t)((d % 3) * 32768);
        #pragma unroll
        for (int i = 0; i < 8; i++) {
            int idx = tid + i * 256, r = idx >> 4, q = idx & 15;
            uint32_t off = (uint32_t)((q>>3)*16384) + SWZ128((uint32_t)(r*128 + (q&7)*16));
            CP_ASYNC16(base + off, &WOT[(size_t)(d0 + r) * DH + q*4]);
        }
    };

    #pragma unroll
    for (int i = 0; i < 8; i++) {
        int idx = tid + i * 256, r = idx >> 4, q = idx & 15;
        uint32_t off = (uint32_t)((q>>3)*16384) + SWZ128((uint32_t)(r*128 + (q&7)*16));
        CP_ASYNC16(sZ + off, &g_z[((size_t)h*SQ + s0 + r) * DH + q*4]);
    }
    prefetch_w(0);
    CP_COMMIT();
    prefetch_w(1);
    CP_COMMIT();

    const int r0 = mw + (lane >> 2);
    const int ec = (lane & 3) * 2;

    #pragma unroll 1
    for (int d = 0; d < 8; d++) {
        CP_WAIT(1);
        __syncthreads();
        if (d + 2 < 8) prefetch_w(d + 2);
        CP_COMMIT();

        const uint32_t sbW = sW + (uint32_t)((d % 3) * 32768);
        float acc[16][4] = {};

        #pragma unroll
        for (int ks = 0; ks < 8; ks++) {
            uint32_t a[4];
            {
                int row = mw + ((g & 1) << 3) + l7;
                int byo = (ks & 3)*32 + ((g >> 1) << 4);
                ldsm_x4(a[0], a[1], a[2], a[3],
                        sZ + (uint32_t)((ks >> 2)*16384) + SWZ128((uint32_t)(row*128 + byo)));
            }
            uint32_t b[32];
            #pragma unroll
            for (int nb = 0; nb < 8; nb++) {
                int row = nb * 16 + ((g >> 1) << 3) + l7;
                int byo = (ks & 3)*32 + ((g & 1) << 4);
                ldsm_x4(b[nb*4+0], b[nb*4+1], b[nb*4+2], b[nb*4+3],
                        sbW + (uint32_t)((ks >> 2)*16384) + SWZ128((uint32_t)(row*128 + byo)));
            }
            #pragma unroll
            for (int ni = 0; ni < 16; ni++)
                mma_tf32(acc[ni], a, b[(ni >> 1)*4 + (ni & 1)*2],
                                     b[(ni >> 1)*4 + (ni & 1)*2 + 1]);
        }

        const int d0 = d * 128;
        #pragma unroll
        for (int ni = 0; ni < 16; ni++) {
            int dg = d0 + ni*8 + ec;
            float b0 = bO[dg] * 0.0625f, b1 = bO[dg + 1] * 0.0625f;
            int sg0 = s0 + r0, sg1 = sg0 + 8;
            *(float2*)&out[((size_t)sg0 * NH + h) * DM + dg] =
                make_float2(acc[ni][0] + b0, acc[ni][1] + b1);
            *(float2*)&out[((size_t)sg1 * NH + h) * DM + dg] =
                make_float2(acc[ni][2] + b0, acc[ni][3] + b1);
        }
    }
}

// -------------------------------------------------------------------------------
extern "C" void kernel_launch(void* const* d_in, const int* in_sizes, int n_in,
                              void* d_out, int out_size)
{
    (void)in_sizes; (void)n_in; (void)out_size;
    const float* xq = (const float*)d_in[0];
    const float* xk = (const float*)d_in[1];
    const float* xv = (const float*)d_in[2];
    const float* WQ = (const float*)d_in[3];
    const float* bQ = (const float*)d_in[4];
    const float* WK = (const float*)d_in[5];
    const float* bK = (const float*)d_in[6];
    const float* WV = (const float*)d_in[7];
    const float* bV = (const float*)d_in[8];
    const float* WO = (const float*)d_in[9];
    const float* bO = (const float*)d_in[10];
    float* out = (float*)d_out;

    static int smem_set = 0;
    if (!smem_set) {
        cudaFuncSetAttribute(attn_mma_kernel,
                             cudaFuncAttributeMaxDynamicSharedMemorySize, 81920);
        cudaFuncSetAttribute(proj_mma_kernel,
                             cudaFuncAttributeMaxDynamicSharedMemorySize, 98304);
        cudaFuncSetAttribute(outproj_mma_kernel,
                             cudaFuncAttributeMaxDynamicSharedMemorySize, 131072);
        smem_set = 1;
    }

    rope_tab_kernel<<<256, 256>>>();
    transpose_w_kernel<<<dim3(64, 64), dim3(32, 8)>>>(WQ, WK, WV, WO);
    proj_mma_kernel<<<dim3(16, 16, 3), 256, 98304>>>(xq, xk, xv, bQ, bK, bV);
    attn_mma_kernel<<<dim3(16, 16), 128, 81920>>>();
    outproj_mma_kernel<<<dim3(16, 16), 256, 131072>>>(bO, out);
}

// round 11
// speedup vs baseline: 1.1211x; 1.0298x over previous
#include <cuda_runtime.h>
#include <cstdint>
#include <math.h>

#define SQ 2048
#define NH 16
#define DM 1024
#define DH 64

__device__ float g_q[NH * SQ * DH];       // pre-scaled by log2e/8, tf32-rounded
__device__ float g_k[NH * SQ * DH];
__device__ float g_vt[NH * DH * SQ];      // V^T: [h][e][s], tf32-rounded
__device__ float g_z[NH * SQ * DH];
__device__ float g_wt[3][NH * DH * DM];   // W^T, tf32-rounded
__device__ float g_wot[NH * DM * DH];     // W_O^T, tf32-rounded
__device__ float2 g_rope[SQ * 32];        // (sin, cos) per (pos, j)

__device__ __forceinline__ uint32_t smem_u32(const void* p) {
    uint32_t a;
    asm("{ .reg .u64 t; cvta.to.shared.u64 t, %1; cvt.u32.u64 %0, t; }" : "=r"(a) : "l"(p));
    return a;
}
#define SWZ128(x) ((x) ^ (((x) >> 3) & 0x70))

__device__ __forceinline__ float to_tf32(float x) {
    float y;
    asm("cvt.rna.tf32.f32 %0, %1;" : "=f"(y) : "f"(x));
    return y;
}
__device__ __forceinline__ float ex2(float x) {
    float y;
    asm("ex2.approx.ftz.f32 %0, %1;" : "=f"(y) : "f"(x));
    return y;
}
__device__ __forceinline__ void ldsm_x4(uint32_t& r0, uint32_t& r1, uint32_t& r2,
                                        uint32_t& r3, uint32_t addr) {
    asm volatile("ldmatrix.sync.aligned.m8n8.x4.shared.b16 {%0,%1,%2,%3}, [%4];"
                 : "=r"(r0), "=r"(r1), "=r"(r2), "=r"(r3) : "r"(addr));
}
__device__ __forceinline__ void mma_tf32(float* c, const uint32_t* a,
                                         uint32_t b0, uint32_t b1) {
    asm volatile(
        "mma.sync.aligned.m16n8k8.row.col.f32.tf32.tf32.f32 "
        "{%0,%1,%2,%3}, {%4,%5,%6,%7}, {%8,%9}, {%0,%1,%2,%3};"
        : "+f"(c[0]), "+f"(c[1]), "+f"(c[2]), "+f"(c[3])
        : "r"(a[0]), "r"(a[1]), "r"(a[2]), "r"(a[3]), "r"(b0), "r"(b1));
}
#define CP_ASYNC16(dst, src) \
    asm volatile("cp.async.cg.shared.global [%0], [%1], 16;" :: "r"(dst), "l"(src))
#define CP_COMMIT() asm volatile("cp.async.commit_group;" ::: "memory")
#define CP_WAIT(n)  asm volatile("cp.async.wait_group %0;" :: "n"(n) : "memory")

// ---------------- RoPE table ----------------------------------------------------
__global__ void rope_tab_kernel()
{
    const int idx = blockIdx.x * 256 + threadIdx.x;
    const int pos = idx >> 5, j = idx & 31;
    const float L2B = 0.41524101186092029f;           // log2(10000)/32
    float invf = exp2f(-(float)j * L2B);
    float sn, cs;
    sincosf((float)pos * invf, &sn, &cs);
    g_rope[idx] = make_float2(sn, cs);
}

// ---------------- W transpose (+tf32 round) -----------------------------------
__global__ void transpose_w_kernel(const float* __restrict__ WQ, const float* __restrict__ WK,
                                   const float* __restrict__ WV, const float* __restrict__ WO)
{
    __shared__ float t[32][33];
    const int m = blockIdx.y >> 4, h = blockIdx.y & 15;
    const float* src; float* dst; int R, C;
    if (m == 0)      { src = WQ + (size_t)h*DM*DH; dst = g_wt[0] + (size_t)h*DH*DM; R = DM; C = DH; }
    else if (m == 1) { src = WK + (size_t)h*DM*DH; dst = g_wt[1] + (size_t)h*DH*DM; R = DM; C = DH; }
    else if (m == 2) { src = WV + (size_t)h*DM*DH; dst = g_wt[2] + (size_t)h*DH*DM; R = DM; C = DH; }
    else             { src = WO + (size_t)h*DH*DM; dst = g_wot   + (size_t)h*DM*DH; R = DH; C = DM; }
    const int nrt = R / 32, rt = blockIdx.x % nrt, ct = blockIdx.x / nrt;
    const int x = ct * 32 + threadIdx.x;
    #pragma unroll
    for (int j = 0; j < 4; j++)
        t[threadIdx.y + j*8][threadIdx.x] =
            to_tf32(src[(size_t)(rt*32 + threadIdx.y + j*8) * C + x]);
    __syncthreads();
    const int xo = rt * 32 + threadIdx.x;
    #pragma unroll
    for (int j = 0; j < 4; j++)
        dst[(size_t)(ct*32 + threadIdx.y + j*8) * R + xo] = t[threadIdx.x][threadIdx.y + j*8];
}

// ---------------- Projection via HMMA tf32, 4-stage cp.async -------------------
__global__ __launch_bounds__(256, 1) void proj_mma_kernel(
    const float* __restrict__ xq, const float* __restrict__ xk, const float* __restrict__ xv,
    const float* __restrict__ bQ, const float* __restrict__ bK, const float* __restrict__ bV)
{
    extern __shared__ uint8_t dsm[];
    const uint32_t sA = smem_u32(dsm);
    const uint32_t sB = sA + 65536;

    const int tid = threadIdx.x, w = tid >> 5, lane = tid & 31;
    const int h = blockIdx.y, which = blockIdx.z;
    const int s0 = blockIdx.x * 128;

    const float* X    = (which == 0) ? xq : (which == 1) ? xk : xv;
    const float* bias = (which == 0) ? bQ : (which == 1) ? bK : bV;
    const float* WT   = g_wt[which] + (size_t)h * DH * DM;

    const int mw = w * 16;
    const int g  = lane >> 3, l7 = lane & 7;

    auto prefetch = [&](int c) {
        const int k0 = c * 32;
        const uint32_t ab = sA + (uint32_t)((c & 3) * 16384);
        const uint32_t bb = sB + (uint32_t)((c & 3) * 8192);
        #pragma unroll
        for (int i = 0; i < 4; i++) {
            int idx = tid + i * 256, r = idx >> 3, q = idx & 7;
            CP_ASYNC16(ab + SWZ128((uint32_t)(r*128 + q*16)),
                       &X[(((size_t)(s0 + r)) * NH + h) * DM + k0 + q*4]);
        }
        #pragma unroll
        for (int i = 0; i < 2; i++) {
            int idx = tid + i * 256, n = idx >> 3, q = idx & 7;
            CP_ASYNC16(bb + SWZ128((uint32_t)(n*128 + q*16)),
                       &WT[(size_t)n * DM + k0 + q*4]);
        }
    };

    float acc[8][4] = {};

    prefetch(0); CP_COMMIT();
    prefetch(1); CP_COMMIT();
    prefetch(2); CP_COMMIT();

    #pragma unroll 1
    for (int c = 0; c < 32; c++) {
        CP_WAIT(2);
        __syncthreads();
        if (c + 3 < 32) prefetch(c + 3);
        CP_COMMIT();

        const uint32_t sbA = sA + (uint32_t)((c & 3) * 16384);
        const uint32_t sbB = sB + (uint32_t)((c & 3) * 8192);
        #pragma unroll
        for (int kk = 0; kk < 4; kk++) {
            const int kb = kk * 32;
            uint32_t a[4];
            {
                int row = mw + ((g & 1) << 3) + l7;
                int byo = kb + ((g >> 1) << 4);
                ldsm_x4(a[0], a[1], a[2], a[3], sbA + SWZ128((uint32_t)(row*128 + byo)));
            }
            uint32_t b[16];
            #pragma unroll
            for (int nb = 0; nb < 4; nb++) {
                int row = nb * 16 + ((g >> 1) << 3) + l7;
                int byo = kb + ((g & 1) << 4);
                ldsm_x4(b[nb*4+0], b[nb*4+1], b[nb*4+2], b[nb*4+3],
                        sbB + SWZ128((uint32_t)(row*128 + byo)));
            }
            #pragma unroll
            for (int ni = 0; ni < 8; ni++)
                mma_tf32(acc[ni], a, b[(ni >> 1)*4 + (ni & 1)*2],
                                     b[(ni >> 1)*4 + (ni & 1)*2 + 1]);
        }
    }

    const int r0 = mw + (lane >> 2);
    const int ec = (lane & 3) * 2;

    #pragma unroll
    for (int ni = 0; ni < 8; ni++) {
        float bv0 = bias[h * DH + ni*8 + ec];
        float bv1 = bias[h * DH + ni*8 + ec + 1];
        acc[ni][0] += bv0; acc[ni][1] += bv1;
        acc[ni][2] += bv0; acc[ni][3] += bv1;
    }

    if (which < 2) {
        #pragma unroll
        for (int ni = 0; ni < 4; ni++) {
            #pragma unroll
            for (int cc = 0; cc < 2; cc++) {
                int j = ni*8 + ec + cc;
                #pragma unroll
                for (int rr = 0; rr < 2; rr++) {
                    float2 sc = g_rope[(s0 + r0 + rr*8) * 32 + j];
                    int ci = rr*2 + cc;
                    float x = acc[ni][ci], y = acc[ni+4][ci];
                    acc[ni][ci]   = x*sc.y - y*sc.x;
                    acc[ni+4][ci] = y*sc.y + x*sc.x;
                }
            }
        }
    }

    if (which == 2) {
        #pragma unroll
        for (int ni = 0; ni < 8; ni++) {
            int e = ni*8 + ec;
            int sg0 = s0 + r0, sg1 = sg0 + 8;
            g_vt[((size_t)h*DH + e    ) * SQ + sg0] = to_tf32(acc[ni][0]);
            g_vt[((size_t)h*DH + e + 1) * SQ + sg0] = to_tf32(acc[ni][1]);
            g_vt[((size_t)h*DH + e    ) * SQ + sg1] = to_tf32(acc[ni][2]);
            g_vt[((size_t)h*DH + e + 1) * SQ + sg1] = to_tf32(acc[ni][3]);
        }
    } else {
        const float osc = (which == 0) ? 0.18033688011112042f : 1.0f;   // log2e/8
        float* out = (which == 0) ? g_q : g_k;
        #pragma unroll
        for (int ni = 0; ni < 8; ni++) {
            int e = ni*8 + ec;
            *(float2*)&out[((size_t)h*SQ + s0 + r0    ) * DH + e] =
                make_float2(to_tf32(acc[ni][0]*osc), to_tf32(acc[ni][1]*osc));
            *(float2*)&out[((size_t)h*SQ + s0 + r0 + 8) * DH + e] =
                make_float2(to_tf32(acc[ni][2]*osc), to_tf32(acc[ni][3]*osc));
        }
    }
}

// ---------------- Attention via HMMA tf32; P stays in registers -----------------
// dynamic smem: Q @0 (16KB), K @16384 (2x16KB), V @49152 (2x16KB) = 80KB
__global__ __launch_bounds__(128, 2) void attn_mma_kernel()
{
    extern __shared__ uint8_t dsm[];
    const uint32_t sQ = smem_u32(dsm);
    const uint32_t sK = sQ + 16384;
    const uint32_t sV = sQ + 49152;

    const int tid = threadIdx.x, w = tid >> 5, lane = tid & 31;
    const int h = blockIdx.y;
    const int g = lane >> 3, l7 = lane & 7;
    const int mw = w * 16;
    const int r_loc = lane >> 2, ec = (lane & 3) * 2;
    const int t2 = lane & 3;
    const int srcA = (lane & ~3) | (t2 >> 1);   // quad lane holding col t
    const int srcB = srcA + 2;                  // quad lane holding col t+4
    const bool odd = (t2 & 1);

    for (int rep = 0; rep < 2; rep++) {
        const int qb = rep ? (31 - (int)blockIdx.x) : (int)blockIdx.x;
        const int q0 = qb * 64;

        __syncthreads();
        #pragma unroll
        for (int i = 0; i < 8; i++) {
            int idx = tid + i * 128, r = idx >> 4, q = idx & 15;
            uint32_t off = (uint32_t)((q>>3)*8192) + SWZ128((uint32_t)(r*128 + (q&7)*16));
            CP_ASYNC16(sQ + off, &g_q[((size_t)h*SQ + q0 + r) * DH + q*4]);
        }
        CP_COMMIT();
        #pragma unroll
        for (int i = 0; i < 8; i++) {
            int idx = tid + i * 128, r = idx >> 4, q = idx & 15;
            uint32_t off = (uint32_t)((q>>3)*8192) + SWZ128((uint32_t)(r*128 + (q&7)*16));
            CP_ASYNC16(sK + off, &g_k [((size_t)h*SQ + r) * DH + q*4]);
            CP_ASYNC16(sV + off, &g_vt[((size_t)h*DH + r) * SQ + q*4]);
        }
        CP_COMMIT();
        CP_WAIT(1);
        __syncthreads();

        uint32_t qa[8][4];
        #pragma unroll
        for (int ds = 0; ds < 8; ds++) {
            int row = mw + ((g & 1) << 3) + l7;
            int byo = (ds & 3) * 32 + ((g >> 1) << 4);
            ldsm_x4(qa[ds][0], qa[ds][1], qa[ds][2], qa[ds][3],
                    sQ + (uint32_t)((ds >> 2)*8192) + SWZ128((uint32_t)(row*128 + byo)));
        }

        float m0 = -1e30f, m1 = -1e30f, l0 = 0.f, l1 = 0.f;
        float oa[8][4] = {};

        for (int kt = 0; kt <= qb; kt++) {
            const uint32_t kb_off = (uint32_t)((kt & 1) * 16384);
            CP_WAIT(0);
            __syncthreads();
            if (kt < qb) {
                const int kk0 = (kt + 1) * 64;
                const uint32_t nb_off = (uint32_t)(((kt + 1) & 1) * 16384);
                #pragma unroll
                for (int i = 0; i < 8; i++) {
                    int idx = tid + i * 128, r = idx >> 4, q = idx & 15;
                    uint32_t off = nb_off + (uint32_t)((q>>3)*8192)
                                 + SWZ128((uint32_t)(r*128 + (q&7)*16));
                    CP_ASYNC16(sK + off, &g_k [((size_t)h*SQ + kk0 + r) * DH + q*4]);
                    CP_ASYNC16(sV + off, &g_vt[((size_t)h*DH + r) * SQ + kk0 + q*4]);
                }
                CP_COMMIT();
            }

            float sacc[8][4] = {};
            #pragma unroll
            for (int ds = 0; ds < 8; ds++) {
                uint32_t b[16];
                #pragma unroll
                for (int nb = 0; nb < 4; nb++) {
                    int row = nb*16 + ((g >> 1) << 3) + l7;
                    int byo = (ds & 3)*32 + ((g & 1) << 4);
                    ldsm_x4(b[nb*4+0], b[nb*4+1], b[nb*4+2], b[nb*4+3],
                            sK + kb_off + (uint32_t)((ds >> 2)*8192)
                               + SWZ128((uint32_t)(row*128 + byo)));
                }
                #pragma unroll
                for (int ni = 0; ni < 8; ni++)
                    mma_tf32(sacc[ni], qa[ds], b[(ni>>1)*4 + (ni&1)*2],
                                               b[(ni>>1)*4 + (ni&1)*2 + 1]);
            }

            const bool diag = (kt == qb);
            if (diag) {
                #pragma unroll
                for (int ni = 0; ni < 8; ni++) {
                    int col = ni*8 + ec;
                    int row0 = mw + r_loc, row1 = row0 + 8;
                    if (col     > row0) sacc[ni][0] = -1e30f;
                    if (col + 1 > row0) sacc[ni][1] = -1e30f;
                    if (col     > row1) sacc[ni][2] = -1e30f;
                    if (col + 1 > row1) sacc[ni][3] = -1e30f;
                }
            }

            float rx0 = -1e30f, rx1 = -1e30f;
            #pragma unroll
            for (int ni = 0; ni < 8; ni++) {
                rx0 = fmaxf(rx0, fmaxf(sacc[ni][0], sacc[ni][1]));
                rx1 = fmaxf(rx1, fmaxf(sacc[ni][2], sacc[ni][3]));
            }
            rx0 = fmaxf(rx0, __shfl_xor_sync(0xffffffffu, rx0, 1));
            rx0 = fmaxf(rx0, __shfl_xor_sync(0xffffffffu, rx0, 2));
            rx1 = fmaxf(rx1, __shfl_xor_sync(0xffffffffu, rx1, 1));
            rx1 = fmaxf(rx1, __shfl_xor_sync(0xffffffffu, rx1, 2));
            float mn0 = fmaxf(m0, rx0), mn1 = fmaxf(m1, rx1);
            float c0 = ex2(m0 - mn0), c1 = ex2(m1 - mn1);
            float su0 = 0.f, su1 = 0.f;
            #pragma unroll
            for (int ni = 0; ni < 8; ni++) {
                sacc[ni][0] = ex2(sacc[ni][0] - mn0);
                sacc[ni][1] = ex2(sacc[ni][1] - mn0);
                sacc[ni][2] = ex2(sacc[ni][2] - mn1);
                sacc[ni][3] = ex2(sacc[ni][3] - mn1);
                su0 += sacc[ni][0] + sacc[ni][1];
                su1 += sacc[ni][2] + sacc[ni][3];
            }
            su0 += __shfl_xor_sync(0xffffffffu, su0, 1);
            su0 += __shfl_xor_sync(0xffffffffu, su0, 2);
            su1 += __shfl_xor_sync(0xffffffffu, su1, 1);
            su1 += __shfl_xor_sync(0xffffffffu, su1, 2);
            l0 = l0 * c0 + su0; l1 = l1 * c1 + su1;
            m0 = mn0; m1 = mn1;
            #pragma unroll
            for (int ni = 0; ni < 8; ni++) {
                oa[ni][0] *= c0; oa[ni][1] *= c0;
                oa[ni][2] *= c1; oa[ni][3] *= c1;
            }

            // round P once (rna), then build PV A-fragments via quad shuffles
            #pragma unroll
            for (int ni = 0; ni < 8; ni++) {
                sacc[ni][0] = to_tf32(sacc[ni][0]);
                sacc[ni][1] = to_tf32(sacc[ni][1]);
                sacc[ni][2] = to_tf32(sacc[ni][2]);
                sacc[ni][3] = to_tf32(sacc[ni][3]);
            }

            #pragma unroll
            for (int ks = 0; ks < 8; ks++) {
                // A fragment for k-chunk ks from sacc[ks] (P cols 8ks..8ks+7)
                float v00 = __shfl_sync(0xffffffffu, sacc[ks][0], srcA);
                float v01 = __shfl_sync(0xffffffffu, sacc[ks][1], srcA);
                float v20 = __shfl_sync(0xffffffffu, sacc[ks][2], srcA);
                float v21 = __shfl_sync(0xffffffffu, sacc[ks][3], srcA);
                float w00 = __shfl_sync(0xffffffffu, sacc[ks][0], srcB);
                float w01 = __shfl_sync(0xffffffffu, sacc[ks][1], srcB);
                float w20 = __shfl_sync(0xffffffffu, sacc[ks][2], srcB);
                float w21 = __shfl_sync(0xffffffffu, sacc[ks][3], srcB);
                uint32_t a[4];
                a[0] = __float_as_uint(odd ? v01 : v00);
                a[1] = __float_as_uint(odd ? v21 : v20);
                a[2] = __float_as_uint(odd ? w01 : w00);
                a[3] = __float_as_uint(odd ? w21 : w20);

                uint32_t b[16];
                #pragma unroll
                for (int nb = 0; nb < 4; nb++) {
                    int rowb = nb*16 + ((g >> 1) << 3) + l7;
                    int byob = (ks & 3)*32 + ((g & 1) << 4);
                    ldsm_x4(b[nb*4+0], b[nb*4+1], b[nb*4+2], b[nb*4+3],
                            sV + kb_off + (uint32_t)((ks >> 2)*8192)
                               + SWZ128((uint32_t)(rowb*128 + byob)));
                }
                #pragma unroll
                for (int ni = 0; ni < 8; ni++)
                    mma_tf32(oa[ni], a, b[(ni>>1)*4 + (ni&1)*2],
                                        b[(ni>>1)*4 + (ni&1)*2 + 1]);
            }
        }

        float inv0 = 1.f / l0, inv1 = 1.f / l1;
        int row0 = q0 + mw + r_loc;
        #pragma unroll
        for (int ni = 0; ni < 8; ni++) {
            int e = ni*8 + ec;
            *(float2*)&g_z[((size_t)h*SQ + row0    ) * DH + e] =
                make_float2(to_tf32(oa[ni][0]*inv0), to_tf32(oa[ni][1]*inv0));
            *(float2*)&g_z[((size_t)h*SQ + row0 + 8) * DH + e] =
                make_float2(to_tf32(oa[ni][2]*inv1), to_tf32(oa[ni][3]*inv1));
        }
    }
}

// ---------------- Output projection, persistent over d-tiles --------------------
__global__ __launch_bounds__(256, 1) void outproj_mma_kernel(
    const float* __restrict__ bO, float* __restrict__ out)
{
    extern __shared__ uint8_t dsm[];
    const uint32_t sZ = smem_u32(dsm);
    const uint32_t sW = sZ + 32768;

    const int tid = threadIdx.x, w = tid >> 5, lane = tid & 31;
    const int s0 = blockIdx.x * 128, h = blockIdx.y;
    const float* WOT = g_wot + (size_t)h * DM * DH;

    const int mw = w * 16;
    const int g  = lane >> 3, l7 = lane & 7;

    auto prefetch_w = [&](int d) {
        const int d0 = d * 128;
        const uint32_t base = sW + (uint32_t)((d % 3) * 32768);
        #pragma unroll
        for (int i = 0; i < 8; i++) {
            int idx = tid + i * 256, r = idx >> 4, q = idx & 15;
            uint32_t off = (uint32_t)((q>>3)*16384) + SWZ128((uint32_t)(r*128 + (q&7)*16));
            CP_ASYNC16(base + off, &WOT[(size_t)(d0 + r) * DH + q*4]);
        }
    };

    #pragma unroll
    for (int i = 0; i < 8; i++) {
        int idx = tid + i * 256, r = idx >> 4, q = idx & 15;
        uint32_t off = (uint32_t)((q>>3)*16384) + SWZ128((uint32_t)(r*128 + (q&7)*16));
        CP_ASYNC16(sZ + off, &g_z[((size_t)h*SQ + s0 + r) * DH + q*4]);
    }
    prefetch_w(0);
    CP_COMMIT();
    prefetch_w(1);
    CP_COMMIT();

    const int r0 = mw + (lane >> 2);
    const int ec = (lane & 3) * 2;

    #pragma unroll 1
    for (int d = 0; d < 8; d++) {
        CP_WAIT(1);
        __syncthreads();
        if (d + 2 < 8) prefetch_w(d + 2);
        CP_COMMIT();

        const uint32_t sbW = sW + (uint32_t)((d % 3) * 32768);
        float acc[16][4] = {};

        #pragma unroll
        for (int ks = 0; ks < 8; ks++) {
            uint32_t a[4];
            {
                int row = mw + ((g & 1) << 3) + l7;
                int byo = (ks & 3)*32 + ((g >> 1) << 4);
                ldsm_x4(a[0], a[1], a[2], a[3],
                        sZ + (uint32_t)((ks >> 2)*16384) + SWZ128((uint32_t)(row*128 + byo)));
            }
            uint32_t b[32];
            #pragma unroll
            for (int nb = 0; nb < 8; nb++) {
                int row = nb * 16 + ((g >> 1) << 3) + l7;
                int byo = (ks & 3)*32 + ((g & 1) << 4);
                ldsm_x4(b[nb*4+0], b[nb*4+1], b[nb*4+2], b[nb*4+3],
                        sbW + (uint32_t)((ks >> 2)*16384) + SWZ128((uint32_t)(row*128 + byo)));
            }
            #pragma unroll
            for (int ni = 0; ni < 16; ni++)
                mma_tf32(acc[ni], a, b[(ni >> 1)*4 + (ni & 1)*2],
                                     b[(ni >> 1)*4 + (ni & 1)*2 + 1]);
        }

        const int d0 = d * 128;
        #pragma unroll
        for (int ni = 0; ni < 16; ni++) {
            int dg = d0 + ni*8 + ec;
            float b0 = bO[dg] * 0.0625f, b1 = bO[dg + 1] * 0.0625f;
            int sg0 = s0 + r0, sg1 = sg0 + 8;
            *(float2*)&out[((size_t)sg0 * NH + h) * DM + dg] =
                make_float2(acc[ni][0] + b0, acc[ni][1] + b1);
            *(float2*)&out[((size_t)sg1 * NH + h) * DM + dg] =
                make_float2(acc[ni][2] + b0, acc[ni][3] + b1);
        }
    }
}

// -------------------------------------------------------------------------------
extern "C" void kernel_launch(void* const* d_in, const int* in_sizes, int n_in,
                              void* d_out, int out_size)
{
    (void)in_sizes; (void)n_in; (void)out_size;
    const float* xq = (const float*)d_in[0];
    const float* xk = (const float*)d_in[1];
    const float* xv = (const float*)d_in[2];
    const float* WQ = (const float*)d_in[3];
    const float* bQ = (const float*)d_in[4];
    const float* WK = (const float*)d_in[5];
    const float* bK = (const float*)d_in[6];
    const float* WV = (const float*)d_in[7];
    const float* bV = (const float*)d_in[8];
    const float* WO = (const float*)d_in[9];
    const float* bO = (const float*)d_in[10];
    float* out = (float*)d_out;

    static int smem_set = 0;
    if (!smem_set) {
        cudaFuncSetAttribute(attn_mma_kernel,
                             cudaFuncAttributeMaxDynamicSharedMemorySize, 81920);
        cudaFuncSetAttribute(proj_mma_kernel,
                             cudaFuncAttributeMaxDynamicSharedMemorySize, 98304);
        cudaFuncSetAttribute(outproj_mma_kernel,
                             cudaFuncAttributeMaxDynamicSharedMemorySize, 131072);
        smem_set = 1;
    }

    rope_tab_kernel<<<256, 256>>>();
    transpose_w_kernel<<<dim3(64, 64), dim3(32, 8)>>>(WQ, WK, WV, WO);
    proj_mma_kernel<<<dim3(16, 16, 3), 256, 98304>>>(xq, xk, xv, bQ, bK, bV);
    attn_mma_kernel<<<dim3(16, 16), 128, 81920>>>();
    outproj_mma_kernel<<<dim3(16, 16), 256, 131072>>>(bO, out);
}

// round 12
// speedup vs baseline: 1.2833x; 1.1446x over previous
#include <cuda_runtime.h>
#include <cuda_fp16.h>
#include <cstdint>
#include <math.h>

#define SQ 2048
#define NH 16
#define DM 1024
#define DH 64

__device__ __half g_q[NH * SQ * DH];      // pre-scaled by log2e/8, fp16
__device__ __half g_k[NH * SQ * DH];      // fp16
__device__ __half g_vt[NH * DH * SQ];     // V^T: [h][e][s], fp16
__device__ float  g_z[NH * SQ * DH];
__device__ float  g_wt[3][NH * DH * DM];  // W^T, tf32-rounded
__device__ float  g_wot[NH * DM * DH];    // W_O^T, tf32-rounded
__device__ float2 g_rope[SQ * 32];        // (sin, cos) per (pos, j)

__device__ __forceinline__ uint32_t smem_u32(const void* p) {
    uint32_t a;
    asm("{ .reg .u64 t; cvta.to.shared.u64 t, %1; cvt.u32.u64 %0, t; }" : "=r"(a) : "l"(p));
    return a;
}
#define SWZ128(x) ((x) ^ (((x) >> 3) & 0x70))

__device__ __forceinline__ float to_tf32(float x) {
    float y;
    asm("cvt.rna.tf32.f32 %0, %1;" : "=f"(y) : "f"(x));
    return y;
}
__device__ __forceinline__ float ex2(float x) {
    float y;
    asm("ex2.approx.ftz.f32 %0, %1;" : "=f"(y) : "f"(x));
    return y;
}
__device__ __forceinline__ uint32_t packh2(float lo, float hi) {
    uint32_t r;
    asm("cvt.rn.f16x2.f32 %0, %1, %2;" : "=r"(r) : "f"(hi), "f"(lo));
    return r;
}
__device__ __forceinline__ void ldsm_x4(uint32_t& r0, uint32_t& r1, uint32_t& r2,
                                        uint32_t& r3, uint32_t addr) {
    asm volatile("ldmatrix.sync.aligned.m8n8.x4.shared.b16 {%0,%1,%2,%3}, [%4];"
                 : "=r"(r0), "=r"(r1), "=r"(r2), "=r"(r3) : "r"(addr));
}
__device__ __forceinline__ void mma_tf32(float* c, const uint32_t* a,
                                         uint32_t b0, uint32_t b1) {
    asm volatile(
        "mma.sync.aligned.m16n8k8.row.col.f32.tf32.tf32.f32 "
        "{%0,%1,%2,%3}, {%4,%5,%6,%7}, {%8,%9}, {%0,%1,%2,%3};"
        : "+f"(c[0]), "+f"(c[1]), "+f"(c[2]), "+f"(c[3])
        : "r"(a[0]), "r"(a[1]), "r"(a[2]), "r"(a[3]), "r"(b0), "r"(b1));
}
__device__ __forceinline__ void mma_f16(float* c, const uint32_t* a,
                                        uint32_t b0, uint32_t b1) {
    asm volatile(
        "mma.sync.aligned.m16n8k16.row.col.f32.f16.f16.f32 "
        "{%0,%1,%2,%3}, {%4,%5,%6,%7}, {%8,%9}, {%0,%1,%2,%3};"
        : "+f"(c[0]), "+f"(c[1]), "+f"(c[2]), "+f"(c[3])
        : "r"(a[0]), "r"(a[1]), "r"(a[2]), "r"(a[3]), "r"(b0), "r"(b1));
}
#define CP_ASYNC16(dst, src) \
    asm volatile("cp.async.cg.shared.global [%0], [%1], 16;" :: "r"(dst), "l"(src))
#define CP_COMMIT() asm volatile("cp.async.commit_group;" ::: "memory")
#define CP_WAIT(n)  asm volatile("cp.async.wait_group %0;" :: "n"(n) : "memory")

// ---------------- RoPE table ----------------------------------------------------
__global__ void rope_tab_kernel()
{
    const int idx = blockIdx.x * 256 + threadIdx.x;
    const int pos = idx >> 5, j = idx & 31;
    const float L2B = 0.41524101186092029f;           // log2(10000)/32
    float invf = exp2f(-(float)j * L2B);
    float sn, cs;
    sincosf((float)pos * invf, &sn, &cs);
    g_rope[idx] = make_float2(sn, cs);
}

// ---------------- W transpose (+tf32 round) -----------------------------------
__global__ void transpose_w_kernel(const float* __restrict__ WQ, const float* __restrict__ WK,
                                   const float* __restrict__ WV, const float* __restrict__ WO)
{
    __shared__ float t[32][33];
    const int m = blockIdx.y >> 4, h = blockIdx.y & 15;
    const float* src; float* dst; int R, C;
    if (m == 0)      { src = WQ + (size_t)h*DM*DH; dst = g_wt[0] + (size_t)h*DH*DM; R = DM; C = DH; }
    else if (m == 1) { src = WK + (size_t)h*DM*DH; dst = g_wt[1] + (size_t)h*DH*DM; R = DM; C = DH; }
    else if (m == 2) { src = WV + (size_t)h*DM*DH; dst = g_wt[2] + (size_t)h*DH*DM; R = DM; C = DH; }
    else             { src = WO + (size_t)h*DH*DM; dst = g_wot   + (size_t)h*DM*DH; R = DH; C = DM; }
    const int nrt = R / 32, rt = blockIdx.x % nrt, ct = blockIdx.x / nrt;
    const int x = ct * 32 + threadIdx.x;
    #pragma unroll
    for (int j = 0; j < 4; j++)
        t[threadIdx.y + j*8][threadIdx.x] =
            to_tf32(src[(size_t)(rt*32 + threadIdx.y + j*8) * C + x]);
    __syncthreads();
    const int xo = rt * 32 + threadIdx.x;
    #pragma unroll
    for (int j = 0; j < 4; j++)
        dst[(size_t)(ct*32 + threadIdx.y + j*8) * R + xo] = t[threadIdx.x][threadIdx.y + j*8];
}

// ---------------- Projection via HMMA tf32, 4-stage cp.async -------------------
__global__ __launch_bounds__(256, 1) void proj_mma_kernel(
    const float* __restrict__ xq, const float* __restrict__ xk, const float* __restrict__ xv,
    const float* __restrict__ bQ, const float* __restrict__ bK, const float* __restrict__ bV)
{
    extern __shared__ uint8_t dsm[];
    const uint32_t sA = smem_u32(dsm);
    const uint32_t sB = sA + 65536;

    const int tid = threadIdx.x, w = tid >> 5, lane = tid & 31;
    const int h = blockIdx.y, which = blockIdx.z;
    const int s0 = blockIdx.x * 128;

    const float* X    = (which == 0) ? xq : (which == 1) ? xk : xv;
    const float* bias = (which == 0) ? bQ : (which == 1) ? bK : bV;
    const float* WT   = g_wt[which] + (size_t)h * DH * DM;

    const int mw = w * 16;
    const int g  = lane >> 3, l7 = lane & 7;

    auto prefetch = [&](int c) {
        const int k0 = c * 32;
        const uint32_t ab = sA + (uint32_t)((c & 3) * 16384);
        const uint32_t bb = sB + (uint32_t)((c & 3) * 8192);
        #pragma unroll
        for (int i = 0; i < 4; i++) {
            int idx = tid + i * 256, r = idx >> 3, q = idx & 7;
            CP_ASYNC16(ab + SWZ128((uint32_t)(r*128 + q*16)),
                       &X[(((size_t)(s0 + r)) * NH + h) * DM + k0 + q*4]);
        }
        #pragma unroll
        for (int i = 0; i < 2; i++) {
            int idx = tid + i * 256, n = idx >> 3, q = idx & 7;
            CP_ASYNC16(bb + SWZ128((uint32_t)(n*128 + q*16)),
                       &WT[(size_t)n * DM + k0 + q*4]);
        }
    };

    float acc[8][4] = {};

    prefetch(0); CP_COMMIT();
    prefetch(1); CP_COMMIT();
    prefetch(2); CP_COMMIT();

    #pragma unroll 1
    for (int c = 0; c < 32; c++) {
        CP_WAIT(2);
        __syncthreads();
        if (c + 3 < 32) prefetch(c + 3);
        CP_COMMIT();

        const uint32_t sbA = sA + (uint32_t)((c & 3) * 16384);
        const uint32_t sbB = sB + (uint32_t)((c & 3) * 8192);
        #pragma unroll
        for (int kk = 0; kk < 4; kk++) {
            const int kb = kk * 32;
            uint32_t a[4];
            {
                int row = mw + ((g & 1) << 3) + l7;
                int byo = kb + ((g >> 1) << 4);
                ldsm_x4(a[0], a[1], a[2], a[3], sbA + SWZ128((uint32_t)(row*128 + byo)));
            }
            uint32_t b[16];
            #pragma unroll
            for (int nb = 0; nb < 4; nb++) {
                int row = nb * 16 + ((g >> 1) << 3) + l7;
                int byo = kb + ((g & 1) << 4);
                ldsm_x4(b[nb*4+0], b[nb*4+1], b[nb*4+2], b[nb*4+3],
                        sbB + SWZ128((uint32_t)(row*128 + byo)));
            }
            #pragma unroll
            for (int ni = 0; ni < 8; ni++)
                mma_tf32(acc[ni], a, b[(ni >> 1)*4 + (ni & 1)*2],
                                     b[(ni >> 1)*4 + (ni & 1)*2 + 1]);
        }
    }

    const int r0 = mw + (lane >> 2);
    const int ec = (lane & 3) * 2;

    #pragma unroll
    for (int ni = 0; ni < 8; ni++) {
        float bv0 = bias[h * DH + ni*8 + ec];
        float bv1 = bias[h * DH + ni*8 + ec + 1];
        acc[ni][0] += bv0; acc[ni][1] += bv1;
        acc[ni][2] += bv0; acc[ni][3] += bv1;
    }

    if (which < 2) {
        #pragma unroll
        for (int ni = 0; ni < 4; ni++) {
            #pragma unroll
            for (int cc = 0; cc < 2; cc++) {
                int j = ni*8 + ec + cc;
                #pragma unroll
                for (int rr = 0; rr < 2; rr++) {
                    float2 sc = g_rope[(s0 + r0 + rr*8) * 32 + j];
                    int ci = rr*2 + cc;
                    float x = acc[ni][ci], y = acc[ni+4][ci];
                    acc[ni][ci]   = x*sc.y - y*sc.x;
                    acc[ni+4][ci] = y*sc.y + x*sc.x;
                }
            }
        }
    }

    if (which == 2) {
        #pragma unroll
        for (int ni = 0; ni < 8; ni++) {
            int e = ni*8 + ec;
            int sg0 = s0 + r0, sg1 = sg0 + 8;
            g_vt[((size_t)h*DH + e    ) * SQ + sg0] = __float2half_rn(acc[ni][0]);
            g_vt[((size_t)h*DH + e + 1) * SQ + sg0] = __float2half_rn(acc[ni][1]);
            g_vt[((size_t)h*DH + e    ) * SQ + sg1] = __float2half_rn(acc[ni][2]);
            g_vt[((size_t)h*DH + e + 1) * SQ + sg1] = __float2half_rn(acc[ni][3]);
        }
    } else {
        const float osc = (which == 0) ? 0.18033688011112042f : 1.0f;   // log2e/8
        __half* out = (which == 0) ? g_q : g_k;
        #pragma unroll
        for (int ni = 0; ni < 8; ni++) {
            int e = ni*8 + ec;
            *(uint32_t*)&out[((size_t)h*SQ + s0 + r0    ) * DH + e] =
                packh2(acc[ni][0]*osc, acc[ni][1]*osc);
            *(uint32_t*)&out[((size_t)h*SQ + s0 + r0 + 8) * DH + e] =
                packh2(acc[ni][2]*osc, acc[ni][3]*osc);
        }
    }
}

// ---------------- Attention via HMMA fp16 (f32 accum); P in registers -----------
// dynamic smem: Q @0 (8KB), K @8192 (2x8KB), V @24576 (2x8KB) = 40KB
__global__ __launch_bounds__(128, 2) void attn_mma_kernel()
{
    extern __shared__ uint8_t dsm[];
    const uint32_t sQ = smem_u32(dsm);
    const uint32_t sK = sQ + 8192;
    const uint32_t sV = sQ + 24576;

    const int tid = threadIdx.x, w = tid >> 5, lane = tid & 31;
    const int h = blockIdx.y;
    const int g = lane >> 3, l7 = lane & 7;
    const int mw = w * 16;
    const int r_loc = lane >> 2, ec = (lane & 3) * 2;

    auto load_kv = [&](int kt) {
        const int kk0 = kt * 64;
        const uint32_t boff = (uint32_t)((kt & 1) * 8192);
        #pragma unroll
        for (int i = 0; i < 4; i++) {
            int idx = tid + i * 128, r = idx >> 3, q = idx & 7;
            uint32_t off = boff + SWZ128((uint32_t)(r*128 + q*16));
            CP_ASYNC16(sK + off, &g_k [((size_t)h*SQ + kk0 + r) * DH + q*8]);
            CP_ASYNC16(sV + off, &g_vt[((size_t)h*DH + r) * SQ + kk0 + q*8]);
        }
    };

    for (int rep = 0; rep < 2; rep++) {
        const int qb = rep ? (31 - (int)blockIdx.x) : (int)blockIdx.x;
        const int q0 = qb * 64;

        __syncthreads();
        #pragma unroll
        for (int i = 0; i < 4; i++) {            // Q tile 64x64 fp16 = 8KB
            int idx = tid + i * 128, r = idx >> 3, q = idx & 7;
            CP_ASYNC16(sQ + SWZ128((uint32_t)(r*128 + q*16)),
                       &g_q[((size_t)h*SQ + q0 + r) * DH + q*8]);
        }
        CP_COMMIT();
        load_kv(0);
        CP_COMMIT();
        CP_WAIT(1);
        __syncthreads();

        uint32_t qa[4][4];                       // 4 k16-chunks
        #pragma unroll
        for (int kc = 0; kc < 4; kc++) {
            int row = mw + ((g & 1) << 3) + l7;
            int byo = kc*32 + ((g >> 1) << 4);
            ldsm_x4(qa[kc][0], qa[kc][1], qa[kc][2], qa[kc][3],
                    sQ + SWZ128((uint32_t)(row*128 + byo)));
        }

        float m0 = -1e30f, m1 = -1e30f, l0 = 0.f, l1 = 0.f;
        float oa[8][4] = {};

        for (int kt = 0; kt <= qb; kt++) {
            const uint32_t kb_off = (uint32_t)((kt & 1) * 8192);
            CP_WAIT(0);
            __syncthreads();
            if (kt < qb) load_kv(kt + 1);
            CP_COMMIT();

            // S = Q K^T
            float sacc[8][4] = {};
            #pragma unroll
            for (int kc = 0; kc < 4; kc++) {
                uint32_t b[16];
                #pragma unroll
                for (int nb = 0; nb < 4; nb++) {
                    int row = nb*16 + ((g >> 1) << 3) + l7;
                    int byo = kc*32 + ((g & 1) << 4);
                    ldsm_x4(b[nb*4+0], b[nb*4+1], b[nb*4+2], b[nb*4+3],
                            sK + kb_off + SWZ128((uint32_t)(row*128 + byo)));
                }
                #pragma unroll
                for (int ni = 0; ni < 8; ni++)
                    mma_f16(sacc[ni], qa[kc], b[(ni>>1)*4 + (ni&1)*2],
                                              b[(ni>>1)*4 + (ni&1)*2 + 1]);
            }

            const bool diag = (kt == qb);
            if (diag) {
                #pragma unroll
                for (int ni = 0; ni < 8; ni++) {
                    int col = ni*8 + ec;
                    int row0 = mw + r_loc, row1 = row0 + 8;
                    if (col     > row0) sacc[ni][0] = -1e30f;
                    if (col + 1 > row0) sacc[ni][1] = -1e30f;
                    if (col     > row1) sacc[ni][2] = -1e30f;
                    if (col + 1 > row1) sacc[ni][3] = -1e30f;
                }
            }

            float rx0 = -1e30f, rx1 = -1e30f;
            #pragma unroll
            for (int ni = 0; ni < 8; ni++) {
                rx0 = fmaxf(rx0, fmaxf(sacc[ni][0], sacc[ni][1]));
                rx1 = fmaxf(rx1, fmaxf(sacc[ni][2], sacc[ni][3]));
            }
            rx0 = fmaxf(rx0, __shfl_xor_sync(0xffffffffu, rx0, 1));
            rx0 = fmaxf(rx0, __shfl_xor_sync(0xffffffffu, rx0, 2));
            rx1 = fmaxf(rx1, __shfl_xor_sync(0xffffffffu, rx1, 1));
            rx1 = fmaxf(rx1, __shfl_xor_sync(0xffffffffu, rx1, 2));
            float mn0 = fmaxf(m0, rx0), mn1 = fmaxf(m1, rx1);
            float c0 = ex2(m0 - mn0), c1 = ex2(m1 - mn1);
            float su0 = 0.f, su1 = 0.f;
            #pragma unroll
            for (int ni = 0; ni < 8; ni++) {
                sacc[ni][0] = ex2(sacc[ni][0] - mn0);
                sacc[ni][1] = ex2(sacc[ni][1] - mn0);
                sacc[ni][2] = ex2(sacc[ni][2] - mn1);
                sacc[ni][3] = ex2(sacc[ni][3] - mn1);
                su0 += sacc[ni][0] + sacc[ni][1];
                su1 += sacc[ni][2] + sacc[ni][3];
            }
            su0 += __shfl_xor_sync(0xffffffffu, su0, 1);
            su0 += __shfl_xor_sync(0xffffffffu, su0, 2);
            su1 += __shfl_xor_sync(0xffffffffu, su1, 1);
            su1 += __shfl_xor_sync(0xffffffffu, su1, 2);
            l0 = l0 * c0 + su0; l1 = l1 * c1 + su1;
            m0 = mn0; m1 = mn1;
            #pragma unroll
            for (int ni = 0; ni < 8; ni++) {
                oa[ni][0] *= c0; oa[ni][1] *= c0;
                oa[ni][2] *= c1; oa[ni][3] *= c1;
            }

            // O += P V   (A-fragments are pure packs of sacc — fp16 layout magic)
            #pragma unroll
            for (int ks = 0; ks < 4; ks++) {
                uint32_t a[4];
                a[0] = packh2(sacc[2*ks  ][0], sacc[2*ks  ][1]);
                a[1] = packh2(sacc[2*ks  ][2], sacc[2*ks  ][3]);
                a[2] = packh2(sacc[2*ks+1][0], sacc[2*ks+1][1]);
                a[3] = packh2(sacc[2*ks+1][2], sacc[2*ks+1][3]);

                uint32_t b[16];
                #pragma unroll
                for (int nb = 0; nb < 4; nb++) {
                    int rowb = nb*16 + ((g >> 1) << 3) + l7;
                    int byob = ks*32 + ((g & 1) << 4);
                    ldsm_x4(b[nb*4+0], b[nb*4+1], b[nb*4+2], b[nb*4+3],
                            sV + kb_off + SWZ128((uint32_t)(rowb*128 + byob)));
                }
                #pragma unroll
                for (int ni = 0; ni < 8; ni++)
                    mma_f16(oa[ni], a, b[(ni>>1)*4 + (ni&1)*2],
                                       b[(ni>>1)*4 + (ni&1)*2 + 1]);
            }
        }

        float inv0 = 1.f / l0, inv1 = 1.f / l1;
        int row0 = q0 + mw + r_loc;
        #pragma unroll
        for (int ni = 0; ni < 8; ni++) {
            int e = ni*8 + ec;
            *(float2*)&g_z[((size_t)h*SQ + row0    ) * DH + e] =
                make_float2(to_tf32(oa[ni][0]*inv0), to_tf32(oa[ni][1]*inv0));
            *(float2*)&g_z[((size_t)h*SQ + row0 + 8) * DH + e] =
                make_float2(to_tf32(oa[ni][2]*inv1), to_tf32(oa[ni][3]*inv1));
        }
    }
}

// ---------------- Output projection, persistent over d-tiles --------------------
__global__ __launch_bounds__(256, 1) void outproj_mma_kernel(
    const float* __restrict__ bO, float* __restrict__ out)
{
    extern __shared__ uint8_t dsm[];
    const uint32_t sZ = smem_u32(dsm);
    const uint32_t sW = sZ + 32768;

    const int tid = threadIdx.x, w = tid >> 5, lane = tid & 31;
    const int s0 = blockIdx.x * 128, h = blockIdx.y;
    const float* WOT = g_wot + (size_t)h * DM * DH;

    const int mw = w * 16;
    const int g  = lane >> 3, l7 = lane & 7;

    auto prefetch_w = [&](int d) {
        const int d0 = d * 128;
        const uint32_t base = sW + (uint32_t)((d % 3) * 32768);
        #pragma unroll
        for (int i = 0; i < 8; i++) {
            int idx = tid + i * 256, r = idx >> 4, q = idx & 15;
            uint32_t off = (uint32_t)((q>>3)*16384) + SWZ128((uint32_t)(r*128 + (q&7)*16));
            CP_ASYNC16(base + off, &WOT[(size_t)(d0 + r) * DH + q*4]);
        }
    };

    #pragma unroll
    for (int i = 0; i < 8; i++) {
        int idx = tid + i * 256, r = idx >> 4, q = idx & 15;
        uint32_t off = (uint32_t)((q>>3)*16384) + SWZ128((uint32_t)(r*128 + (q&7)*16));
        CP_ASYNC16(sZ + off, &g_z[((size_t)h*SQ + s0 + r) * DH + q*4]);
    }
    prefetch_w(0);
    CP_COMMIT();
    prefetch_w(1);
    CP_COMMIT();

    const int r0 = mw + (lane >> 2);
    const int ec = (lane & 3) * 2;

    #pragma unroll 1
    for (int d = 0; d < 8; d++) {
        CP_WAIT(1);
        __syncthreads();
        if (d + 2 < 8) prefetch_w(d + 2);
        CP_COMMIT();

        const uint32_t sbW = sW + (uint32_t)((d % 3) * 32768);
        float acc[16][4] = {};

        #pragma unroll
        for (int ks = 0; ks < 8; ks++) {
            uint32_t a[4];
            {
                int row = mw + ((g & 1) << 3) + l7;
                int byo = (ks & 3)*32 + ((g >> 1) << 4);
                ldsm_x4(a[0], a[1], a[2], a[3],
                        sZ + (uint32_t)((ks >> 2)*16384) + SWZ128((uint32_t)(row*128 + byo)));
            }
            uint32_t b[32];
            #pragma unroll
            for (int nb = 0; nb < 8; nb++) {
                int row = nb * 16 + ((g >> 1) << 3) + l7;
                int byo = (ks & 3)*32 + ((g & 1) << 4);
                ldsm_x4(b[nb*4+0], b[nb*4+1], b[nb*4+2], b[nb*4+3],
                        sbW + (uint32_t)((ks >> 2)*16384) + SWZ128((uint32_t)(row*128 + byo)));
            }
            #pragma unroll
            for (int ni = 0; ni < 16; ni++)
                mma_tf32(acc[ni], a, b[(ni >> 1)*4 + (ni & 1)*2],
                                     b[(ni >> 1)*4 + (ni & 1)*2 + 1]);
        }

        const int d0 = d * 128;
        #pragma unroll
        for (int ni = 0; ni < 16; ni++) {
            int dg = d0 + ni*8 + ec;
            float b0 = bO[dg] * 0.0625f, b1 = bO[dg + 1] * 0.0625f;
            int sg0 = s0 + r0, sg1 = sg0 + 8;
            *(float2*)&out[((size_t)sg0 * NH + h) * DM + dg] =
                make_float2(acc[ni][0] + b0, acc[ni][1] + b1);
            *(float2*)&out[((size_t)sg1 * NH + h) * DM + dg] =
                make_float2(acc[ni][2] + b0, acc[ni][3] + b1);
        }
    }
}

// -------------------------------------------------------------------------------
extern "C" void kernel_launch(void* const* d_in, const int* in_sizes, int n_in,
                              void* d_out, int out_size)
{
    (void)in_sizes; (void)n_in; (void)out_size;
    const float* xq = (const float*)d_in[0];
    const float* xk = (const float*)d_in[1];
    const float* xv = (const float*)d_in[2];
    const float* WQ = (const float*)d_in[3];
    const float* bQ = (const float*)d_in[4];
    const float* WK = (const float*)d_in[5];
    const float* bK = (const float*)d_in[6];
    const float* WV = (const float*)d_in[7];
    const float* bV = (const float*)d_in[8];
    const float* WO = (const float*)d_in[9];
    const float* bO = (const float*)d_in[10];
    float* out = (float*)d_out;

    static int smem_set = 0;
    if (!smem_set) {
        cudaFuncSetAttribute(attn_mma_kernel,
                             cudaFuncAttributeMaxDynamicSharedMemorySize, 40960);
        cudaFuncSetAttribute(proj_mma_kernel,
                             cudaFuncAttributeMaxDynamicSharedMemorySize, 98304);
        cudaFuncSetAttribute(outproj_mma_kernel,
                             cudaFuncAttributeMaxDynamicSharedMemorySize, 131072);
        smem_set = 1;
    }

    rope_tab_kernel<<<256, 256>>>();
    transpose_w_kernel<<<dim3(64, 64), dim3(32, 8)>>>(WQ, WK, WV, WO);
    proj_mma_kernel<<<dim3(16, 16, 3), 256, 98304>>>(xq, xk, xv, bQ, bK, bV);
    attn_mma_kernel<<<dim3(16, 16), 128, 40960>>>();
    outproj_mma_kernel<<<dim3(16, 16), 256, 131072>>>(bO, out);
}

// round 13
// speedup vs baseline: 1.2897x; 1.0050x over previous
#include <cuda_runtime.h>
#include <cuda_fp16.h>
#include <cstdint>
#include <math.h>

#define SQ 2048
#define NH 16
#define DM 1024
#define DH 64

__device__ __half g_q[NH * SQ * DH];      // pre-scaled by log2e/8, fp16
__device__ __half g_k[NH * SQ * DH];      // fp16
__device__ __half g_vt[NH * DH * SQ];     // V^T: [h][e][s], fp16
__device__ float  g_z[NH * SQ * DH];
__device__ float  g_wt[3][NH * DH * DM];  // W^T, tf32-rounded
__device__ float  g_wot[NH * DM * DH];    // W_O^T, tf32-rounded
__device__ float2 g_rope[SQ * 32];        // (sin, cos) per (pos, j)

__device__ __forceinline__ uint32_t smem_u32(const void* p) {
    uint32_t a;
    asm("{ .reg .u64 t; cvta.to.shared.u64 t, %1; cvt.u32.u64 %0, t; }" : "=r"(a) : "l"(p));
    return a;
}
#define SWZ128(x) ((x) ^ (((x) >> 3) & 0x70))

__device__ __forceinline__ float to_tf32(float x) {
    float y;
    asm("cvt.rna.tf32.f32 %0, %1;" : "=f"(y) : "f"(x));
    return y;
}
__device__ __forceinline__ float ex2(float x) {
    float y;
    asm("ex2.approx.ftz.f32 %0, %1;" : "=f"(y) : "f"(x));
    return y;
}
__device__ __forceinline__ uint32_t packh2(float lo, float hi) {
    uint32_t r;
    asm("cvt.rn.f16x2.f32 %0, %1, %2;" : "=r"(r) : "f"(hi), "f"(lo));
    return r;
}
__device__ __forceinline__ uint32_t h2ex2(uint32_t x) {
    uint32_t y;
    asm("ex2.approx.f16x2 %0, %1;" : "=r"(y) : "r"(x));
    return y;
}
__device__ __forceinline__ void ldsm_x4(uint32_t& r0, uint32_t& r1, uint32_t& r2,
                                        uint32_t& r3, uint32_t addr) {
    asm volatile("ldmatrix.sync.aligned.m8n8.x4.shared.b16 {%0,%1,%2,%3}, [%4];"
                 : "=r"(r0), "=r"(r1), "=r"(r2), "=r"(r3) : "r"(addr));
}
__device__ __forceinline__ void mma_tf32(float* c, const uint32_t* a,
                                         uint32_t b0, uint32_t b1) {
    asm volatile(
        "mma.sync.aligned.m16n8k8.row.col.f32.tf32.tf32.f32 "
        "{%0,%1,%2,%3}, {%4,%5,%6,%7}, {%8,%9}, {%0,%1,%2,%3};"
        : "+f"(c[0]), "+f"(c[1]), "+f"(c[2]), "+f"(c[3])
        : "r"(a[0]), "r"(a[1]), "r"(a[2]), "r"(a[3]), "r"(b0), "r"(b1));
}
__device__ __forceinline__ void mma_f16(float* c, const uint32_t* a,
                                        uint32_t b0, uint32_t b1) {
    asm volatile(
        "mma.sync.aligned.m16n8k16.row.col.f32.f16.f16.f32 "
        "{%0,%1,%2,%3}, {%4,%5,%6,%7}, {%8,%9}, {%0,%1,%2,%3};"
        : "+f"(c[0]), "+f"(c[1]), "+f"(c[2]), "+f"(c[3])
        : "r"(a[0]), "r"(a[1]), "r"(a[2]), "r"(a[3]), "r"(b0), "r"(b1));
}
#define CP_ASYNC16(dst, src) \
    asm volatile("cp.async.cg.shared.global [%0], [%1], 16;" :: "r"(dst), "l"(src))
#define CP_COMMIT() asm volatile("cp.async.commit_group;" ::: "memory")
#define CP_WAIT(n)  asm volatile("cp.async.wait_group %0;" :: "n"(n) : "memory")

// ---------------- RoPE table ----------------------------------------------------
__global__ void rope_tab_kernel()
{
    const int idx = blockIdx.x * 256 + threadIdx.x;
    const int pos = idx >> 5, j = idx & 31;
    const float L2B = 0.41524101186092029f;           // log2(10000)/32
    float invf = exp2f(-(float)j * L2B);
    float sn, cs;
    sincosf((float)pos * invf, &sn, &cs);
    g_rope[idx] = make_float2(sn, cs);
}

// ---------------- W transpose (+tf32 round) -----------------------------------
__global__ void transpose_w_kernel(const float* __restrict__ WQ, const float* __restrict__ WK,
                                   const float* __restrict__ WV, const float* __restrict__ WO)
{
    __shared__ float t[32][33];
    const int m = blockIdx.y >> 4, h = blockIdx.y & 15;
    const float* src; float* dst; int R, C;
    if (m == 0)      { src = WQ + (size_t)h*DM*DH; dst = g_wt[0] + (size_t)h*DH*DM; R = DM; C = DH; }
    else if (m == 1) { src = WK + (size_t)h*DM*DH; dst = g_wt[1] + (size_t)h*DH*DM; R = DM; C = DH; }
    else if (m == 2) { src = WV + (size_t)h*DM*DH; dst = g_wt[2] + (size_t)h*DH*DM; R = DM; C = DH; }
    else             { src = WO + (size_t)h*DH*DM; dst = g_wot   + (size_t)h*DM*DH; R = DH; C = DM; }
    const int nrt = R / 32, rt = blockIdx.x % nrt, ct = blockIdx.x / nrt;
    const int x = ct * 32 + threadIdx.x;
    #pragma unroll
    for (int j = 0; j < 4; j++)
        t[threadIdx.y + j*8][threadIdx.x] =
            to_tf32(src[(size_t)(rt*32 + threadIdx.y + j*8) * C + x]);
    __syncthreads();
    const int xo = rt * 32 + threadIdx.x;
    #pragma unroll
    for (int j = 0; j < 4; j++)
        dst[(size_t)(ct*32 + threadIdx.y + j*8) * R + xo] = t[threadIdx.x][threadIdx.y + j*8];
}

// ---------------- Projection via HMMA tf32, 4-stage cp.async -------------------
__global__ __launch_bounds__(256, 1) void proj_mma_kernel(
    const float* __restrict__ xq, const float* __restrict__ xk, const float* __restrict__ xv,
    const float* __restrict__ bQ, const float* __restrict__ bK, const float* __restrict__ bV)
{
    extern __shared__ uint8_t dsm[];
    const uint32_t sA = smem_u32(dsm);
    const uint32_t sB = sA + 65536;

    const int tid = threadIdx.x, w = tid >> 5, lane = tid & 31;
    const int h = blockIdx.y, which = blockIdx.z;
    const int s0 = blockIdx.x * 128;

    const float* X    = (which == 0) ? xq : (which == 1) ? xk : xv;
    const float* bias = (which == 0) ? bQ : (which == 1) ? bK : bV;
    const float* WT   = g_wt[which] + (size_t)h * DH * DM;

    const int mw = w * 16;
    const int g  = lane >> 3, l7 = lane & 7;

    auto prefetch = [&](int c) {
        const int k0 = c * 32;
        const uint32_t ab = sA + (uint32_t)((c & 3) * 16384);
        const uint32_t bb = sB + (uint32_t)((c & 3) * 8192);
        #pragma unroll
        for (int i = 0; i < 4; i++) {
            int idx = tid + i * 256, r = idx >> 3, q = idx & 7;
            CP_ASYNC16(ab + SWZ128((uint32_t)(r*128 + q*16)),
                       &X[(((size_t)(s0 + r)) * NH + h) * DM + k0 + q*4]);
        }
        #pragma unroll
        for (int i = 0; i < 2; i++) {
            int idx = tid + i * 256, n = idx >> 3, q = idx & 7;
            CP_ASYNC16(bb + SWZ128((uint32_t)(n*128 + q*16)),
                       &WT[(size_t)n * DM + k0 + q*4]);
        }
    };

    float acc[8][4] = {};

    prefetch(0); CP_COMMIT();
    prefetch(1); CP_COMMIT();
    prefetch(2); CP_COMMIT();

    #pragma unroll 1
    for (int c = 0; c < 32; c++) {
        CP_WAIT(2);
        __syncthreads();
        if (c + 3 < 32) prefetch(c + 3);
        CP_COMMIT();

        const uint32_t sbA = sA + (uint32_t)((c & 3) * 16384);
        const uint32_t sbB = sB + (uint32_t)((c & 3) * 8192);
        #pragma unroll
        for (int kk = 0; kk < 4; kk++) {
            const int kb = kk * 32;
            uint32_t a[4];
            {
                int row = mw + ((g & 1) << 3) + l7;
                int byo = kb + ((g >> 1) << 4);
                ldsm_x4(a[0], a[1], a[2], a[3], sbA + SWZ128((uint32_t)(row*128 + byo)));
            }
            uint32_t b[16];
            #pragma unroll
            for (int nb = 0; nb < 4; nb++) {
                int row = nb * 16 + ((g >> 1) << 3) + l7;
                int byo = kb + ((g & 1) << 4);
                ldsm_x4(b[nb*4+0], b[nb*4+1], b[nb*4+2], b[nb*4+3],
                        sbB + SWZ128((uint32_t)(row*128 + byo)));
            }
            #pragma unroll
            for (int ni = 0; ni < 8; ni++)
                mma_tf32(acc[ni], a, b[(ni >> 1)*4 + (ni & 1)*2],
                                     b[(ni >> 1)*4 + (ni & 1)*2 + 1]);
        }
    }

    const int r0 = mw + (lane >> 2);
    const int ec = (lane & 3) * 2;

    #pragma unroll
    for (int ni = 0; ni < 8; ni++) {
        float bv0 = bias[h * DH + ni*8 + ec];
        float bv1 = bias[h * DH + ni*8 + ec + 1];
        acc[ni][0] += bv0; acc[ni][1] += bv1;
        acc[ni][2] += bv0; acc[ni][3] += bv1;
    }

    if (which < 2) {
        #pragma unroll
        for (int ni = 0; ni < 4; ni++) {
            #pragma unroll
            for (int cc = 0; cc < 2; cc++) {
                int j = ni*8 + ec + cc;
                #pragma unroll
                for (int rr = 0; rr < 2; rr++) {
                    float2 sc = g_rope[(s0 + r0 + rr*8) * 32 + j];
                    int ci = rr*2 + cc;
                    float x = acc[ni][ci], y = acc[ni+4][ci];
                    acc[ni][ci]   = x*sc.y - y*sc.x;
                    acc[ni+4][ci] = y*sc.y + x*sc.x;
                }
            }
        }
    }

    if (which == 2) {
        #pragma unroll
        for (int ni = 0; ni < 8; ni++) {
            int e = ni*8 + ec;
            int sg0 = s0 + r0, sg1 = sg0 + 8;
            g_vt[((size_t)h*DH + e    ) * SQ + sg0] = __float2half_rn(acc[ni][0]);
            g_vt[((size_t)h*DH + e + 1) * SQ + sg0] = __float2half_rn(acc[ni][1]);
            g_vt[((size_t)h*DH + e    ) * SQ + sg1] = __float2half_rn(acc[ni][2]);
            g_vt[((size_t)h*DH + e + 1) * SQ + sg1] = __float2half_rn(acc[ni][3]);
        }
    } else {
        const float osc = (which == 0) ? 0.18033688011112042f : 1.0f;   // log2e/8
        __half* out = (which == 0) ? g_q : g_k;
        #pragma unroll
        for (int ni = 0; ni < 8; ni++) {
            int e = ni*8 + ec;
            *(uint32_t*)&out[((size_t)h*SQ + s0 + r0    ) * DH + e] =
                packh2(acc[ni][0]*osc, acc[ni][1]*osc);
            *(uint32_t*)&out[((size_t)h*SQ + s0 + r0 + 8) * DH + e] =
                packh2(acc[ni][2]*osc, acc[ni][3]*osc);
        }
    }
}

// ---------------- Attention: fp16 HMMA; f16x2 exp; row-sum via ones-mma ---------
// dynamic smem: Q @0 (8KB), K @8192 (2x8KB), V @24576 (2x8KB) = 40KB
__global__ __launch_bounds__(128, 2) void attn_mma_kernel()
{
    extern __shared__ uint8_t dsm[];
    const uint32_t sQ = smem_u32(dsm);
    const uint32_t sK = sQ + 8192;
    const uint32_t sV = sQ + 24576;

    const int tid = threadIdx.x, w = tid >> 5, lane = tid & 31;
    const int h = blockIdx.y;
    const int g = lane >> 3, l7 = lane & 7;
    const int mw = w * 16;
    const int r_loc = lane >> 2, ec = (lane & 3) * 2;
    const uint32_t H2ONE = 0x3C003C00u;   // (1.0h, 1.0h)

    auto load_kv = [&](int kt) {
        const int kk0 = kt * 64;
        const uint32_t boff = (uint32_t)((kt & 1) * 8192);
        #pragma unroll
        for (int i = 0; i < 4; i++) {
            int idx = tid + i * 128, r = idx >> 3, q = idx & 7;
            uint32_t off = boff + SWZ128((uint32_t)(r*128 + q*16));
            CP_ASYNC16(sK + off, &g_k [((size_t)h*SQ + kk0 + r) * DH + q*8]);
            CP_ASYNC16(sV + off, &g_vt[((size_t)h*DH + r) * SQ + kk0 + q*8]);
        }
    };

    for (int rep = 0; rep < 2; rep++) {
        const int qb = rep ? (31 - (int)blockIdx.x) : (int)blockIdx.x;
        const int q0 = qb * 64;

        __syncthreads();
        #pragma unroll
        for (int i = 0; i < 4; i++) {
            int idx = tid + i * 128, r = idx >> 3, q = idx & 7;
            CP_ASYNC16(sQ + SWZ128((uint32_t)(r*128 + q*16)),
                       &g_q[((size_t)h*SQ + q0 + r) * DH + q*8]);
        }
        CP_COMMIT();
        load_kv(0);
        CP_COMMIT();
        CP_WAIT(1);
        __syncthreads();

        uint32_t qa[4][4];
        #pragma unroll
        for (int kc = 0; kc < 4; kc++) {
            int row = mw + ((g & 1) << 3) + l7;
            int byo = kc*32 + ((g >> 1) << 4);
            ldsm_x4(qa[kc][0], qa[kc][1], qa[kc][2], qa[kc][3],
                    sQ + SWZ128((uint32_t)(row*128 + byo)));
        }

        float m0 = -1e30f, m1 = -1e30f, l0 = 0.f, l1 = 0.f;
        float oa[8][4] = {};

        for (int kt = 0; kt <= qb; kt++) {
            const uint32_t kb_off = (uint32_t)((kt & 1) * 8192);
            CP_WAIT(0);
            __syncthreads();
            if (kt < qb) load_kv(kt + 1);
            CP_COMMIT();

            // S = Q K^T
            float sacc[8][4] = {};
            #pragma unroll
            for (int kc = 0; kc < 4; kc++) {
                uint32_t b[16];
                #pragma unroll
                for (int nb = 0; nb < 4; nb++) {
                    int row = nb*16 + ((g >> 1) << 3) + l7;
                    int byo = kc*32 + ((g & 1) << 4);
                    ldsm_x4(b[nb*4+0], b[nb*4+1], b[nb*4+2], b[nb*4+3],
                            sK + kb_off + SWZ128((uint32_t)(row*128 + byo)));
                }
                #pragma unroll
                for (int ni = 0; ni < 8; ni++)
                    mma_f16(sacc[ni], qa[kc], b[(ni>>1)*4 + (ni&1)*2],
                                              b[(ni>>1)*4 + (ni&1)*2 + 1]);
            }

            const bool diag = (kt == qb);
            if (diag) {
                #pragma unroll
                for (int ni = 0; ni < 8; ni++) {
                    int col = ni*8 + ec;
                    int row0 = mw + r_loc, row1 = row0 + 8;
                    if (col     > row0) sacc[ni][0] = -1e30f;
                    if (col + 1 > row0) sacc[ni][1] = -1e30f;
                    if (col     > row1) sacc[ni][2] = -1e30f;
                    if (col + 1 > row1) sacc[ni][3] = -1e30f;
                }
            }

            // row max (quad reduction)
            float rx0 = -1e30f, rx1 = -1e30f;
            #pragma unroll
            for (int ni = 0; ni < 8; ni++) {
                rx0 = fmaxf(rx0, fmaxf(sacc[ni][0], sacc[ni][1]));
                rx1 = fmaxf(rx1, fmaxf(sacc[ni][2], sacc[ni][3]));
            }
            rx0 = fmaxf(rx0, __shfl_xor_sync(0xffffffffu, rx0, 1));
            rx0 = fmaxf(rx0, __shfl_xor_sync(0xffffffffu, rx0, 2));
            rx1 = fmaxf(rx1, __shfl_xor_sync(0xffffffffu, rx1, 1));
            rx1 = fmaxf(rx1, __shfl_xor_sync(0xffffffffu, rx1, 2));
            float mn0 = fmaxf(m0, rx0), mn1 = fmaxf(m1, rx1);
            float c0 = ex2(m0 - mn0), c1 = ex2(m1 - mn1);

            // P = exp2(s - m) computed directly in f16x2 (pack then h2-ex2)
            uint32_t prow0[8], prow1[8];
            #pragma unroll
            for (int ni = 0; ni < 8; ni++) {
                prow0[ni] = h2ex2(packh2(sacc[ni][0] - mn0, sacc[ni][1] - mn0));
                prow1[ni] = h2ex2(packh2(sacc[ni][2] - mn1, sacc[ni][3] - mn1));
            }

            m0 = mn0; m1 = mn1;
            #pragma unroll
            for (int ni = 0; ni < 8; ni++) {
                oa[ni][0] *= c0; oa[ni][1] *= c0;
                oa[ni][2] *= c1; oa[ni][3] *= c1;
            }

            // O += P V; row sums via ones-mma (lacc[0]=row0 sum, lacc[2]=row1 sum)
            float lacc[4] = {};
            #pragma unroll
            for (int ks = 0; ks < 4; ks++) {
                uint32_t a[4];
                a[0] = prow0[2*ks];
                a[1] = prow1[2*ks];
                a[2] = prow0[2*ks+1];
                a[3] = prow1[2*ks+1];

                mma_f16(lacc, a, H2ONE, H2ONE);

                uint32_t b[16];
                #pragma unroll
                for (int nb = 0; nb < 4; nb++) {
                    int rowb = nb*16 + ((g >> 1) << 3) + l7;
                    int byob = ks*32 + ((g & 1) << 4);
                    ldsm_x4(b[nb*4+0], b[nb*4+1], b[nb*4+2], b[nb*4+3],
                            sV + kb_off + SWZ128((uint32_t)(rowb*128 + byob)));
                }
                #pragma unroll
                for (int ni = 0; ni < 8; ni++)
                    mma_f16(oa[ni], a, b[(ni>>1)*4 + (ni&1)*2],
                                       b[(ni>>1)*4 + (ni&1)*2 + 1]);
            }
            l0 = l0 * c0 + lacc[0];
            l1 = l1 * c1 + lacc[2];
        }

        float inv0 = 1.f / l0, inv1 = 1.f / l1;
        int row0 = q0 + mw + r_loc;
        #pragma unroll
        for (int ni = 0; ni < 8; ni++) {
            int e = ni*8 + ec;
            *(float2*)&g_z[((size_t)h*SQ + row0    ) * DH + e] =
                make_float2(to_tf32(oa[ni][0]*inv0), to_tf32(oa[ni][1]*inv0));
            *(float2*)&g_z[((size_t)h*SQ + row0 + 8) * DH + e] =
                make_float2(to_tf32(oa[ni][2]*inv1), to_tf32(oa[ni][3]*inv1));
        }
    }
}

// ---------------- Output projection, persistent, d-tile 64, 2 CTAs/SM -----------
// dyn smem: Z @0 (32KB), W @32768 (3x16KB) = 80KB
__global__ __launch_bounds__(256, 2) void outproj_mma_kernel(
    const float* __restrict__ bO, float* __restrict__ out)
{
    extern __shared__ uint8_t dsm[];
    const uint32_t sZ = smem_u32(dsm);
    const uint32_t sW = sZ + 32768;

    const int tid = threadIdx.x, w = tid >> 5, lane = tid & 31;
    const int s0 = blockIdx.x * 128, h = blockIdx.y;
    const float* WOT = g_wot + (size_t)h * DM * DH;

    const int mw = w * 16;
    const int g  = lane >> 3, l7 = lane & 7;

    auto prefetch_w = [&](int d) {
        const int d0 = d * 64;
        const uint32_t base = sW + (uint32_t)((d % 3) * 16384);
        #pragma unroll
        for (int i = 0; i < 4; i++) {
            int idx = tid + i * 256, r = idx >> 4, q = idx & 15;
            uint32_t off = (uint32_t)((q>>3)*8192) + SWZ128((uint32_t)(r*128 + (q&7)*16));
            CP_ASYNC16(base + off, &WOT[(size_t)(d0 + r) * DH + q*4]);
        }
    };

    #pragma unroll
    for (int i = 0; i < 8; i++) {
        int idx = tid + i * 256, r = idx >> 4, q = idx & 15;
        uint32_t off = (uint32_t)((q>>3)*16384) + SWZ128((uint32_t)(r*128 + (q&7)*16));
        CP_ASYNC16(sZ + off, &g_z[((size_t)h*SQ + s0 + r) * DH + q*4]);
    }
    prefetch_w(0);
    CP_COMMIT();
    prefetch_w(1);
    CP_COMMIT();

    const int r0 = mw + (lane >> 2);
    const int ec = (lane & 3) * 2;

    #pragma unroll 1
    for (int d = 0; d < 16; d++) {
        CP_WAIT(1);
        __syncthreads();
        if (d + 2 < 16) prefetch_w(d + 2);
        CP_COMMIT();

        const uint32_t sbW = sW + (uint32_t)((d % 3) * 16384);
        float acc[8][4] = {};

        #pragma unroll
        for (int ks = 0; ks < 8; ks++) {
            uint32_t a[4];
            {
                int row = mw + ((g & 1) << 3) + l7;
                int byo = (ks & 3)*32 + ((g >> 1) << 4);
                ldsm_x4(a[0], a[1], a[2], a[3],
                        sZ + (uint32_t)((ks >> 2)*16384) + SWZ128((uint32_t)(row*128 + byo)));
            }
            uint32_t b[16];
            #pragma unroll
            for (int nb = 0; nb < 4; nb++) {
                int row = nb * 16 + ((g >> 1) << 3) + l7;
                int byo = (ks & 3)*32 + ((g & 1) << 4);
                ldsm_x4(b[nb*4+0], b[nb*4+1], b[nb*4+2], b[nb*4+3],
                        sbW + (uint32_t)((ks >> 2)*8192) + SWZ128((uint32_t)(row*128 + byo)));
            }
            #pragma unroll
            for (int ni = 0; ni < 8; ni++)
                mma_tf32(acc[ni], a, b[(ni >> 1)*4 + (ni & 1)*2],
                                     b[(ni >> 1)*4 + (ni & 1)*2 + 1]);
        }

        const int d0 = d * 64;
        #pragma unroll
        for (int ni = 0; ni < 8; ni++) {
            int dg = d0 + ni*8 + ec;
            float b0 = bO[dg] * 0.0625f, b1 = bO[dg + 1] * 0.0625f;
            int sg0 = s0 + r0, sg1 = sg0 + 8;
            *(float2*)&out[((size_t)sg0 * NH + h) * DM + dg] =
                make_float2(acc[ni][0] + b0, acc[ni][1] + b1);
            *(float2*)&out[((size_t)sg1 * NH + h) * DM + dg] =
                make_float2(acc[ni][2] + b0, acc[ni][3] + b1);
        }
    }
}

// -------------------------------------------------------------------------------
extern "C" void kernel_launch(void* const* d_in, const int* in_sizes, int n_in,
                              void* d_out, int out_size)
{
    (void)in_sizes; (void)n_in; (void)out_size;
    const float* xq = (const float*)d_in[0];
    const float* xk = (const float*)d_in[1];
    const float* xv = (const float*)d_in[2];
    const float* WQ = (const float*)d_in[3];
    const float* bQ = (const float*)d_in[4];
    const float* WK = (const float*)d_in[5];
    const float* bK = (const float*)d_in[6];
    const float* WV = (const float*)d_in[7];
    const float* bV = (const float*)d_in[8];
    const float* WO = (const float*)d_in[9];
    const float* bO = (const float*)d_in[10];
    float* out = (float*)d_out;

    static int smem_set = 0;
    if (!smem_set) {
        cudaFuncSetAttribute(attn_mma_kernel,
                             cudaFuncAttributeMaxDynamicSharedMemorySize, 40960);
        cudaFuncSetAttribute(proj_mma_kernel,
                             cudaFuncAttributeMaxDynamicSharedMemorySize, 98304);
        cudaFuncSetAttribute(outproj_mma_kernel,
                             cudaFuncAttributeMaxDynamicSharedMemorySize, 81920);
        smem_set = 1;
    }

    rope_tab_kernel<<<256, 256>>>();
    transpose_w_kernel<<<dim3(64, 64), dim3(32, 8)>>>(WQ, WK, WV, WO);
    proj_mma_kernel<<<dim3(16, 16, 3), 256, 98304>>>(xq, xk, xv, bQ, bK, bV);
    attn_mma_kernel<<<dim3(16, 16), 128, 40960>>>();
    outproj_mma_kernel<<<dim3(16, 16), 256, 81920>>>(bO, out);
}